// round 1
// baseline (speedup 1.0000x reference)
#include <cuda_runtime.h>
#include <math.h>

#define NN 4096
#define HH 128
#define KM 32
#define KI 20
#define BB 32

// ---------------- output layout (floats) ----------------
#define OFF_H    0
#define OFF_POS  (NN*HH)                 // 524288
#define OFF_F    (OFF_POS + NN*3)        // 536576
#define OFF_S    (OFF_F + NN*3)          // 548864  (3 blocks of N*KI)
#define OFF_CONF (OFF_S + 3*NN*KI)       // 794624
#define OFF_ST   (OFF_CONF + NN*64)      // 1056768

// ---------------- device scratch (no runtime allocs) ----------------
__device__ float g_h[2][NN*HH];
__device__ float g_pos[2][NN*3];
__device__ int   g_idx[NN*KM];
__device__ int   g_cnt[NN];
__device__ int   g_iidx[NN*KI];
__device__ int   g_icnt[NN];
__device__ int   g_seg[BB+1];

__device__ __forceinline__ float silu_f(float x) {
    return x / (1.0f + __expf(-x));
}

// ---------------- batch segment boundaries (batch is sorted) ----------------
__global__ void seg_kernel(const int* __restrict__ batch) {
    int b = threadIdx.x;
    if (b <= BB) {
        int lo = 0, hi = NN;
        while (lo < hi) { int mid = (lo + hi) >> 1; if (batch[mid] < b) lo = mid + 1; else hi = mid; }
        g_seg[b] = lo;
    }
}

__global__ void init_copy(const float* __restrict__ h, const float* __restrict__ p) {
    int i = blockIdx.x * blockDim.x + threadIdx.x;
    if (i < NN*HH) g_h[0][i] = h[i];
    if (i < NN*3)  g_pos[0][i] = p[i];
}

// ---------------- radius graph, k nearest within cutoff, per-thread top-k ----------------
template<int KK, bool INTER>
__global__ void neighbors_kernel(int sel, const int* __restrict__ batch, float cutoff2) {
    int i = blockIdx.x * blockDim.x + threadIdx.x;
    if (i >= NN) return;
    const float* p = g_pos[sel];
    int b  = batch[i];
    int s0 = g_seg[b], s1 = g_seg[b+1];
    float px = p[3*i], py = p[3*i+1], pz = p[3*i+2];
    float bd[KK]; int bj[KK]; int m = 0;
    for (int j = s0; j < s1; j++) {
        if (j == i) continue;
        float dx = px - p[3*j], dy = py - p[3*j+1], dz = pz - p[3*j+2];
        float d2 = dx*dx + dy*dy + dz*dz;
        if (d2 > cutoff2) continue;
        if (m < KK) {
            int q = m++;
            while (q > 0 && bd[q-1] > d2) { bd[q] = bd[q-1]; bj[q] = bj[q-1]; q--; }
            bd[q] = d2; bj[q] = j;
        } else if (d2 < bd[KK-1]) {
            int q = KK - 1;
            while (q > 0 && bd[q-1] > d2) { bd[q] = bd[q-1]; bj[q] = bj[q-1]; q--; }
            bd[q] = d2; bj[q] = j;
        }
    }
    int* oi = INTER ? g_iidx : g_idx;
    int* oc = INTER ? g_icnt : g_cnt;
    for (int e = 0; e < KK; e++) oi[i*KK + e] = (e < m) ? bj[e] : i;
    oc[i] = m;
}

// ---------------- one fused EGNN layer: block = node, thread = output column ----------------
__global__ __launch_bounds__(HH) void egnn_layer(
    int sel,
    const float* __restrict__ ew1, const float* __restrict__ eb1,
    const float* __restrict__ ew2, const float* __restrict__ eb2,
    const float* __restrict__ cw1, const float* __restrict__ cb1,
    const float* __restrict__ cw2,
    const float* __restrict__ nw1, const float* __restrict__ nb1,
    const float* __restrict__ nw2, const float* __restrict__ nb2)
{
    const int i = blockIdx.x, c = threadIdx.x;
    const float* h_in  = g_h[sel];    float* h_out = g_h[sel^1];
    const float* p_in  = g_pos[sel];  float* p_out = g_pos[sel^1];

    __shared__ __align__(16) float s_hjT[HH][36];  // [k][e], pad 36 -> float4-aligned rows
    __shared__ __align__(16) float s_m1T[HH][36];  // m1 transposed; later reused as reduce buf
    __shared__ float s_hi[HH], s_agg[HH], s_n1[HH];
    __shared__ float s_d2[KM], s_rel[3][KM], s_mask[KM], s_cE[KM];
    __shared__ int   s_j[KM];

    s_hi[c] = h_in[i*HH + c];
    if (c < KM) {
        int cnt = g_cnt[i];
        int j = (c < cnt) ? g_idx[i*KM + c] : i;
        s_j[c] = j;
        s_mask[c] = (c < cnt) ? 1.0f : 0.0f;
        float rx = p_in[3*i]   - p_in[3*j];
        float ry = p_in[3*i+1] - p_in[3*j+1];
        float rz = p_in[3*i+2] - p_in[3*j+2];
        s_rel[0][c] = rx; s_rel[1][c] = ry; s_rel[2][c] = rz;
        s_d2[c] = rx*rx + ry*ry + rz*rz;
    }
    __syncthreads();

    // load neighbor features transposed: s_hjT[k][e] = h_j[e][k], k = tid (coalesced gathers)
    #pragma unroll
    for (int e = 0; e < KM; e++) s_hjT[c][e] = h_in[s_j[e]*HH + c];
    __syncthreads();

    float acc[KM];

    // ---- edge GEMM 1: silu([hi|hj|d2] @ ew1 + eb1) ----
    {
        float base = eb1[c];
        #pragma unroll 8
        for (int k = 0; k < HH; k++) base += s_hi[k] * ew1[k*HH + c];
        float wd = ew1[256*HH + c];
        #pragma unroll
        for (int e = 0; e < KM; e++) acc[e] = base + s_d2[e] * wd;
        const float* W = ew1 + HH*HH;  // hj rows
        #pragma unroll 4
        for (int k = 0; k < HH; k++) {
            float w = W[k*HH + c];
            const float4* r4 = reinterpret_cast<const float4*>(s_hjT[k]);
            #pragma unroll
            for (int q = 0; q < KM/4; q++) {
                float4 v = r4[q];
                acc[4*q+0] += v.x*w; acc[4*q+1] += v.y*w;
                acc[4*q+2] += v.z*w; acc[4*q+3] += v.w*w;
            }
        }
        #pragma unroll
        for (int e = 0; e < KM; e++) s_m1T[c][e] = silu_f(acc[e]);
    }
    __syncthreads();

    // ---- edge GEMM 2: m = silu(m1 @ ew2 + eb2) * mask; agg = sum_e m ----
    float aggc = 0.0f;
    {
        #pragma unroll
        for (int e = 0; e < KM; e++) acc[e] = eb2[c];
        #pragma unroll 4
        for (int k = 0; k < HH; k++) {
            float w = ew2[k*HH + c];
            const float4* r4 = reinterpret_cast<const float4*>(s_m1T[k]);
            #pragma unroll
            for (int q = 0; q < KM/4; q++) {
                float4 v = r4[q];
                acc[4*q+0] += v.x*w; acc[4*q+1] += v.y*w;
                acc[4*q+2] += v.z*w; acc[4*q+3] += v.w*w;
            }
        }
        #pragma unroll
        for (int e = 0; e < KM; e++) {
            float me = silu_f(acc[e]) * s_mask[e];
            acc[e] = me; aggc += me;
        }
    }
    s_agg[c] = aggc;
    __syncthreads();
    #pragma unroll
    for (int e = 0; e < KM; e++) s_hjT[c][e] = acc[e];   // mT overwrites hjT (done with it)
    __syncthreads();

    // ---- coord MLP: c_e = silu(m @ cw1 + cb1) @ cw2 ----
    {
        #pragma unroll
        for (int e = 0; e < KM; e++) acc[e] = cb1[c];
        #pragma unroll 4
        for (int k = 0; k < HH; k++) {
            float w = cw1[k*HH + c];
            const float4* r4 = reinterpret_cast<const float4*>(s_hjT[k]);
            #pragma unroll
            for (int q = 0; q < KM/4; q++) {
                float4 v = r4[q];
                acc[4*q+0] += v.x*w; acc[4*q+1] += v.y*w;
                acc[4*q+2] += v.z*w; acc[4*q+3] += v.w*w;
            }
        }
        float w2 = cw2[c];
        float* red = &s_m1T[0][0];   // reuse as [KM][132]
        #pragma unroll
        for (int e = 0; e < KM; e++) red[e*132 + c] = silu_f(acc[e]) * w2;
    }
    __syncthreads();
    if (c < KM) {
        const float* red = &s_m1T[0][0];
        float s = 0.0f;
        #pragma unroll 8
        for (int k = 0; k < HH; k++) s += red[c*132 + k];
        s_cE[c] = s;
    }
    __syncthreads();
    if (c < 3) {
        float dp = 0.0f;
        #pragma unroll
        for (int e = 0; e < KM; e++) dp += s_rel[c][e] * s_cE[e] * s_mask[e];
        float cntf = fmaxf((float)g_cnt[i], 1.0f);
        p_out[3*i + c] = p_in[3*i + c] + dp / cntf;
    }

    // ---- node MLP: h += silu([h|agg] @ nw1 + nb1) @ nw2 + nb2 ----
    float a = nb1[c];
    #pragma unroll 8
    for (int k = 0; k < HH; k++) a += s_hi[k] * nw1[k*HH + c];
    const float* NW = nw1 + HH*HH;
    #pragma unroll 8
    for (int k = 0; k < HH; k++) a += s_agg[k] * NW[k*HH + c];
    s_n1[c] = silu_f(a);
    __syncthreads();
    float o = nb2[c];
    #pragma unroll 8
    for (int k = 0; k < HH; k++) o += s_n1[k] * nw2[k*HH + c];
    h_out[i*HH + c] = s_hi[c] + o;
}

// ---------------- block-wide triple reduction helper ----------------
__device__ __forceinline__ void reduce3(float v0, float v1, float v2,
                                        float* out, float* scr) {
    #pragma unroll
    for (int off = 16; off > 0; off >>= 1) {
        v0 += __shfl_down_sync(0xffffffffu, v0, off);
        v1 += __shfl_down_sync(0xffffffffu, v1, off);
        v2 += __shfl_down_sync(0xffffffffu, v2, off);
    }
    int w = threadIdx.x >> 5;
    if ((threadIdx.x & 31) == 0) { scr[w] = v0; scr[4+w] = v1; scr[8+w] = v2; }
    __syncthreads();
    if (threadIdx.x == 0) {
        out[0] = scr[0]+scr[1]+scr[2]+scr[3];
        out[1] = scr[4]+scr[5]+scr[6]+scr[7];
        out[2] = scr[8]+scr[9]+scr[10]+scr[11];
    }
    __syncthreads();
}

// ---------------- final readout: forces / scores / conformer / steric + h,pos copy ----------------
__global__ __launch_bounds__(HH) void final_kernel(
    const float* __restrict__ fw1, const float* __restrict__ fb1,
    const float* __restrict__ fw2, const float* __restrict__ fb2,
    const float* __restrict__ iw,  const float* __restrict__ ib,
    const float* __restrict__ ccw1, const float* __restrict__ ccb1,
    const float* __restrict__ ccw2, const float* __restrict__ ccb2,
    const float* __restrict__ sw,  const float* __restrict__ sb,
    float* __restrict__ out)
{
    int i = blockIdx.x, c = threadIdx.x;
    const float* h = g_h[0];
    const float* p = g_pos[0];
    __shared__ float s_hi[HH], s_v[HH], s_scr[12], s_a[3], s_r[3];
    __shared__ int s_ij[KI];
    __shared__ float s_dist[KI], s_im[KI];

    s_hi[c] = h[i*HH + c];
    out[OFF_H + i*HH + c] = s_hi[c];
    if (c < 3) out[OFF_POS + 3*i + c] = p[3*i + c];
    if (c < KI) {
        int cnt = g_icnt[i];
        int j = (c < cnt) ? g_iidx[i*KI + c] : i;
        s_ij[c] = j;
        s_im[c] = (c < cnt) ? 1.0f : 0.0f;
        float dx = p[3*i]-p[3*j], dy = p[3*i+1]-p[3*j+1], dz = p[3*i+2]-p[3*j+2];
        s_dist[c] = sqrtf(dx*dx + dy*dy + dz*dz + 1e-12f);
    }
    __syncthreads();

    // forces = tanh(h@fw1+fb1) @ fw2 + fb2
    {
        float a = fb1[c];
        #pragma unroll 8
        for (int k = 0; k < HH; k++) a += s_hi[k] * fw1[k*HH + c];
        float t = tanhf(a);
        reduce3(t*fw2[3*c], t*fw2[3*c+1], t*fw2[3*c+2], s_r, s_scr);
        if (c < 3) out[OFF_F + 3*i + c] = s_r[c] + fb2[c];
    }

    // conformer = relu(h@cw1+cb1) @ cw2 + cb2
    {
        float a = ccb1[c];
        #pragma unroll 8
        for (int k = 0; k < HH; k++) a += s_hi[k] * ccw1[k*HH + c];
        s_v[c] = fmaxf(a, 0.0f);
    }
    __syncthreads();
    if (c < 64) {
        float o = ccb2[c];
        #pragma unroll 8
        for (int k = 0; k < HH; k++) o += s_v[k] * ccw2[k*64 + c];
        out[OFF_CONF + i*64 + c] = o;
    }

    // steric = h @ sw + sb
    reduce3(s_hi[c]*sw[c], 0.0f, 0.0f, s_r, s_scr);
    if (c == 0) out[OFF_ST + i] = s_r[0] + sb[0];

    // interaction scores: sigmoid([hi|hj|dist|dist/10] @ iw_t + ib_t) * mask
    reduce3(s_hi[c]*iw[c], s_hi[c]*iw[258 + c], s_hi[c]*iw[2*258 + c], s_a, s_scr);
    for (int e = 0; e < KI; e++) {
        int j = s_ij[e];
        float hj = h[j*HH + c];
        reduce3(hj*iw[128 + c], hj*iw[258 + 128 + c], hj*iw[2*258 + 128 + c], s_r, s_scr);
        if (c < 3) {
            const float* iwt = iw + c*258;
            float x = s_a[c] + s_r[c] + s_dist[e]*iwt[256] + (s_dist[e]/10.0f)*iwt[257] + ib[c];
            out[OFF_S + c*(NN*KI) + i*KI + e] = (1.0f/(1.0f + __expf(-x))) * s_im[e];
        }
    }
}

// ---------------- host orchestration ----------------
extern "C" void kernel_launch(void* const* d_in, const int* in_sizes, int n_in,
                              void* d_out, int out_size)
{
    const float* h     = (const float*)d_in[0];
    const float* pos   = (const float*)d_in[1];
    const int*   batch = (const int*)  d_in[2];
    const float* ew1   = (const float*)d_in[3];
    const float* eb1   = (const float*)d_in[4];
    const float* ew2   = (const float*)d_in[5];
    const float* eb2   = (const float*)d_in[6];
    const float* cw1   = (const float*)d_in[7];
    const float* cb1   = (const float*)d_in[8];
    const float* cw2   = (const float*)d_in[9];
    const float* nw1   = (const float*)d_in[10];
    const float* nb1   = (const float*)d_in[11];
    const float* nw2   = (const float*)d_in[12];
    const float* nb2   = (const float*)d_in[13];
    const float* fw1   = (const float*)d_in[14];
    const float* fb1   = (const float*)d_in[15];
    const float* fw2   = (const float*)d_in[16];
    const float* fb2   = (const float*)d_in[17];
    const float* iw    = (const float*)d_in[18];
    const float* ib    = (const float*)d_in[19];
    const float* ccw1  = (const float*)d_in[20];
    const float* ccb1  = (const float*)d_in[21];
    const float* ccw2  = (const float*)d_in[22];
    const float* ccb2  = (const float*)d_in[23];
    const float* sw    = (const float*)d_in[24];
    const float* sb    = (const float*)d_in[25];
    float* out = (float*)d_out;

    seg_kernel<<<1, 64>>>(batch);
    init_copy<<<(NN*HH + 255)/256, 256>>>(h, pos);

    const float cut2[3] = {9.0f, 36.0f, 100.0f};
    int sel = 0;
    for (int l = 0; l < 6; l++) {
        if ((l & 1) == 0)
            neighbors_kernel<KM, false><<<(NN + 127)/128, 128>>>(sel, batch, cut2[l/2]);
        egnn_layer<<<NN, HH>>>(sel,
            ew1 + l*257*HH, eb1 + l*HH,
            ew2 + l*HH*HH,  eb2 + l*HH,
            cw1 + l*HH*HH,  cb1 + l*HH,
            cw2 + l*HH,
            nw1 + l*256*HH, nb1 + l*HH,
            nw2 + l*HH*HH,  nb2 + l*HH);
        sel ^= 1;
    }
    // after 6 layers sel == 0: final h/pos live in buffer 0
    neighbors_kernel<KI, true><<<(NN + 127)/128, 128>>>(sel, batch, 100.0f);
    final_kernel<<<NN, HH>>>(fw1, fb1, fw2, fb2, iw, ib,
                             ccw1, ccb1, ccw2, ccb2, sw, sb, out);
}

// round 2
// speedup vs baseline: 1.4085x; 1.4085x over previous
#include <cuda_runtime.h>
#include <math.h>

#define NN 4096
#define HH 128
#define KM 32
#define KI 20
#define BB 32
#define TPAD 36
#define TILE 32

// ---------------- output layout (floats) ----------------
#define OFF_H    0
#define OFF_POS  (NN*HH)
#define OFF_F    (OFF_POS + NN*3)
#define OFF_S    (OFF_F + NN*3)
#define OFF_CONF (OFF_S + 3*NN*KI)
#define OFF_ST   (OFF_CONF + NN*64)

typedef unsigned long long ull;

// ---------------- device scratch ----------------
__device__ float g_h[2][NN*HH];
__device__ float g_pos[2][NN*3];
__device__ float g_A[NN*HH];
__device__ float g_B[NN*HH];
__device__ float g_agg[NN*HH];
__device__ float g_dots[6][NN];
__device__ int   g_idx[NN*KM];
__device__ int   g_cnt[NN];
__device__ int   g_iidx[NN*KI];
__device__ int   g_icnt[NN];
__device__ int   g_seg[BB+1];

__device__ __forceinline__ float silu_f(float x) { return x / (1.0f + __expf(-x)); }

__device__ __forceinline__ ull pack2(float x) {
    ull r;
    asm("mov.b64 %0, {%1, %1};" : "=l"(r) : "r"(__float_as_uint(x)));
    return r;
}
__device__ __forceinline__ void ffma2(ull& a, ull v, ull w) {
    asm("fma.rn.f32x2 %0, %1, %2, %0;" : "+l"(a) : "l"(v), "l"(w));
}
__device__ __forceinline__ float2 unpack2(ull a) {
    unsigned lo, hi;
    asm("mov.b64 {%0, %1}, %2;" : "=r"(lo), "=r"(hi) : "l"(a));
    return make_float2(__uint_as_float(lo), __uint_as_float(hi));
}

// run a packed k-loop over a transposed smem tile: acc[p] covers lanes (2p,2p+1) of 32
__device__ __forceinline__ void gemm_k(ull* acc, const float (*T)[TPAD],
                                       const float* __restrict__ W, int c, int kk) {
    #pragma unroll 4
    for (int k = 0; k < kk; k++) {
        ull w2 = pack2(W[k*HH + c]);
        const ulonglong2* r = reinterpret_cast<const ulonglong2*>(T[k]);
        #pragma unroll
        for (int q = 0; q < 8; q++) {
            ulonglong2 v = r[q];
            ffma2(acc[2*q],   v.x, w2);
            ffma2(acc[2*q+1], v.y, w2);
        }
    }
}

// ---------------- batch segment boundaries ----------------
__global__ void seg_kernel(const int* __restrict__ batch) {
    int b = threadIdx.x;
    if (b <= BB) {
        int lo = 0, hi = NN;
        while (lo < hi) { int mid = (lo + hi) >> 1; if (batch[mid] < b) lo = mid + 1; else hi = mid; }
        g_seg[b] = lo;
    }
}

__global__ void init_copy(const float* __restrict__ h, const float* __restrict__ p) {
    int i = blockIdx.x * blockDim.x + threadIdx.x;
    if (i < NN*HH) g_h[0][i] = h[i];
    if (i < NN*3)  g_pos[0][i] = p[i];
}

// ---------------- radius graph ----------------
template<int KK, bool INTER>
__global__ void neighbors_kernel(int sel, const int* __restrict__ batch, float cutoff2) {
    int i = blockIdx.x * blockDim.x + threadIdx.x;
    if (i >= NN) return;
    const float* p = g_pos[sel];
    int b  = batch[i];
    int s0 = g_seg[b], s1 = g_seg[b+1];
    float px = p[3*i], py = p[3*i+1], pz = p[3*i+2];
    float bd[KK]; int bj[KK]; int m = 0;
    for (int j = s0; j < s1; j++) {
        if (j == i) continue;
        float dx = px - p[3*j], dy = py - p[3*j+1], dz = pz - p[3*j+2];
        float d2 = dx*dx + dy*dy + dz*dz;
        if (d2 > cutoff2) continue;
        if (m < KK) {
            int q = m++;
            while (q > 0 && bd[q-1] > d2) { bd[q] = bd[q-1]; bj[q] = bj[q-1]; q--; }
            bd[q] = d2; bj[q] = j;
        } else if (d2 < bd[KK-1]) {
            int q = KK - 1;
            while (q > 0 && bd[q-1] > d2) { bd[q] = bd[q-1]; bj[q] = bj[q-1]; q--; }
            bd[q] = d2; bj[q] = j;
        }
    }
    int* oi = INTER ? g_iidx : g_idx;
    int* oc = INTER ? g_icnt : g_cnt;
    for (int e = 0; e < KK; e++) oi[i*KK + e] = (e < m) ? bj[e] : i;
    oc[i] = m;
}

// ---------------- per-layer precompute: A = h@W1a + eb1, B = h@W1b ----------------
__global__ __launch_bounds__(HH) void pre_kernel(int sel, const float* __restrict__ ew1,
                                                 const float* __restrict__ eb1) {
    int n0 = blockIdx.x * TILE, c = threadIdx.x;
    const float* h = g_h[sel];
    __shared__ __align__(16) float s_hT[HH][TPAD];
    #pragma unroll
    for (int e = 0; e < TILE; e++) s_hT[c][e] = h[(n0+e)*HH + c];
    __syncthreads();

    ull acc[16];
    ull b2 = pack2(eb1[c]);
    #pragma unroll
    for (int q = 0; q < 16; q++) acc[q] = b2;
    gemm_k(acc, s_hT, ew1, c, HH);
    #pragma unroll
    for (int p = 0; p < 16; p++) {
        float2 f = unpack2(acc[p]);
        g_A[(n0+2*p)*HH + c]   = f.x;
        g_A[(n0+2*p+1)*HH + c] = f.y;
    }
    ull z = pack2(0.0f);
    #pragma unroll
    for (int q = 0; q < 16; q++) acc[q] = z;
    gemm_k(acc, s_hT, ew1 + HH*HH, c, HH);
    #pragma unroll
    for (int p = 0; p < 16; p++) {
        float2 f = unpack2(acc[p]);
        g_B[(n0+2*p)*HH + c]   = f.x;
        g_B[(n0+2*p+1)*HH + c] = f.y;
    }
}

// ---------------- per-edge kernel: m1 -> m (GEMM2) -> coord MLP -> pos update + agg ----------------
__global__ __launch_bounds__(HH, 5) void edge_kernel(
    int sel,
    const float* __restrict__ ew1d,   // d2 weight row (ew1 + 256*HH)
    const float* __restrict__ ew2, const float* __restrict__ eb2,
    const float* __restrict__ cw1, const float* __restrict__ cb1,
    const float* __restrict__ cw2)
{
    const int i = blockIdx.x, c = threadIdx.x;
    const float* p_in = g_pos[sel];
    float* p_out = g_pos[sel^1];

    __shared__ __align__(16) float s_T1[HH][TPAD];
    __shared__ __align__(16) float s_T2[HH][TPAD];
    __shared__ float s_d2[KM], s_rel[3][KM], s_mask[KM], s_cE[KM];
    __shared__ int   s_j[KM];

    if (c < KM) {
        int cnt = g_cnt[i];
        int j = (c < cnt) ? g_idx[i*KM + c] : i;
        s_j[c] = j;
        s_mask[c] = (c < cnt) ? 1.0f : 0.0f;
        float rx = p_in[3*i]   - p_in[3*j];
        float ry = p_in[3*i+1] - p_in[3*j+1];
        float rz = p_in[3*i+2] - p_in[3*j+2];
        s_rel[0][c] = rx; s_rel[1][c] = ry; s_rel[2][c] = rz;
        s_d2[c] = rx*rx + ry*ry + rz*rz;
    }
    __syncthreads();

    // m1T[c][e] = silu(A[i][c] + B[j][c] + d2*wd[c])   (GEMM1 eliminated by linearity)
    {
        float base = g_A[i*HH + c];
        float wd = ew1d[c];
        #pragma unroll
        for (int e = 0; e < KM; e++) {
            float v = g_B[s_j[e]*HH + c];
            s_T1[c][e] = silu_f(fmaf(s_d2[e], wd, base + v));
        }
    }
    __syncthreads();

    ull acc[16];

    // GEMM2: m = silu(m1@ew2 + eb2) * mask ; agg = sum_e m
    {
        ull b2 = pack2(eb2[c]);
        #pragma unroll
        for (int q = 0; q < 16; q++) acc[q] = b2;
        gemm_k(acc, s_T1, ew2, c, HH);
        float aggc = 0.0f;
        #pragma unroll
        for (int p = 0; p < 16; p++) {
            float2 f = unpack2(acc[p]);
            float m0 = silu_f(f.x) * s_mask[2*p];
            float m1 = silu_f(f.y) * s_mask[2*p+1];
            s_T2[c][2*p] = m0; s_T2[c][2*p+1] = m1;
            aggc += m0 + m1;
        }
        g_agg[i*HH + c] = aggc;
    }
    __syncthreads();

    // coord MLP: cE = silu(m@cw1 + cb1) @ cw2
    {
        ull b2 = pack2(cb1[c]);
        #pragma unroll
        for (int q = 0; q < 16; q++) acc[q] = b2;
        gemm_k(acc, s_T2, cw1, c, HH);
        float w2 = cw2[c];
        float* red = &s_T1[0][0];   // reuse as [KM][132]
        #pragma unroll
        for (int p = 0; p < 16; p++) {
            float2 f = unpack2(acc[p]);
            red[(2*p)*132 + c]   = silu_f(f.x) * w2;
            red[(2*p+1)*132 + c] = silu_f(f.y) * w2;
        }
    }
    __syncthreads();
    if (c < KM) {
        const float* red = &s_T1[0][0];
        float s = 0.0f;
        #pragma unroll 8
        for (int k = 0; k < HH; k++) s += red[c*132 + k];
        s_cE[c] = s;
    }
    __syncthreads();
    if (c < 3) {
        float dp = 0.0f;
        #pragma unroll
        for (int e = 0; e < KM; e++) dp += s_rel[c][e] * s_cE[e] * s_mask[e];
        float cntf = fmaxf((float)g_cnt[i], 1.0f);
        p_out[3*i + c] = p_in[3*i + c] + dp / cntf;
    }
}

// ---------------- node MLP (tiled): h_out = h + silu([h|agg]@nw1+nb1)@nw2+nb2 ----------------
__global__ __launch_bounds__(HH) void node_kernel(
    int sel,
    const float* __restrict__ nw1, const float* __restrict__ nb1,
    const float* __restrict__ nw2, const float* __restrict__ nb2)
{
    int n0 = blockIdx.x * TILE, c = threadIdx.x;
    const float* h_in = g_h[sel];
    float* h_out = g_h[sel^1];
    __shared__ __align__(16) float s_hT[HH][TPAD];
    __shared__ __align__(16) float s_aT[HH][TPAD];
    #pragma unroll
    for (int e = 0; e < TILE; e++) s_hT[c][e] = h_in[(n0+e)*HH + c];
    #pragma unroll
    for (int e = 0; e < TILE; e++) s_aT[c][e] = g_agg[(n0+e)*HH + c];
    __syncthreads();

    ull acc[16];
    ull b2 = pack2(nb1[c]);
    #pragma unroll
    for (int q = 0; q < 16; q++) acc[q] = b2;
    gemm_k(acc, s_hT, nw1, c, HH);
    gemm_k(acc, s_aT, nw1 + HH*HH, c, HH);
    __syncthreads();             // everyone done reading s_aT
    #pragma unroll
    for (int p = 0; p < 16; p++) {
        float2 f = unpack2(acc[p]);
        s_aT[c][2*p]   = silu_f(f.x);
        s_aT[c][2*p+1] = silu_f(f.y);
    }
    __syncthreads();

    b2 = pack2(nb2[c]);
    #pragma unroll
    for (int q = 0; q < 16; q++) acc[q] = b2;
    gemm_k(acc, s_aT, nw2, c, HH);
    #pragma unroll
    for (int p = 0; p < 16; p++) {
        float2 f = unpack2(acc[p]);
        h_out[(n0+2*p)*HH + c]   = s_hT[c][2*p]   + f.x;
        h_out[(n0+2*p+1)*HH + c] = s_hT[c][2*p+1] + f.y;
    }
}

// ---------------- final per-node-tile readout: forces/conformer/steric/dots + h,pos copy ----------------
__global__ __launch_bounds__(HH) void final_tile_kernel(
    const float* __restrict__ fw1, const float* __restrict__ fb1,
    const float* __restrict__ fw2, const float* __restrict__ fb2,
    const float* __restrict__ ccw1, const float* __restrict__ ccb1,
    const float* __restrict__ ccw2, const float* __restrict__ ccb2,
    const float* __restrict__ sw,  const float* __restrict__ sb,
    const float* __restrict__ iw,
    float* __restrict__ out)
{
    int n0 = blockIdx.x * TILE, c = threadIdx.x;
    const float* h = g_h[0];
    const float* p = g_pos[0];
    __shared__ __align__(16) float s_hT[HH][TPAD];
    __shared__ __align__(16) float s_tT[HH][TPAD];

    #pragma unroll
    for (int e = 0; e < TILE; e++) {
        float v = h[(n0+e)*HH + c];
        s_hT[c][e] = v;
        out[OFF_H + (n0+e)*HH + c] = v;
    }
    if (c < 3) {
        for (int e = 0; e < TILE; e++)
            out[OFF_POS + (n0+e)*3 + c] = p[(n0+e)*3 + c];
    }
    __syncthreads();

    ull acc[16];

    // forces hidden: tanh(h@fw1 + fb1)
    ull b2 = pack2(fb1[c]);
    #pragma unroll
    for (int q = 0; q < 16; q++) acc[q] = b2;
    gemm_k(acc, s_hT, fw1, c, HH);
    #pragma unroll
    for (int p2 = 0; p2 < 16; p2++) {
        float2 f = unpack2(acc[p2]);
        s_tT[c][2*p2]   = tanhf(f.x);
        s_tT[c][2*p2+1] = tanhf(f.y);
    }
    __syncthreads();
    if (c < 96) {
        int e = c / 3, t = c % 3;
        float s = 0.0f;
        #pragma unroll 8
        for (int k = 0; k < HH; k++) s += s_tT[k][e] * fw2[k*3 + t];
        out[OFF_F + (n0+e)*3 + t] = s + fb2[t];
    }

    // steric + interaction dots (per node reductions over s_hT columns)
    if (c < TILE) {
        float s = 0.0f;
        #pragma unroll 8
        for (int k = 0; k < HH; k++) s += s_hT[k][c] * sw[k];
        out[OFF_ST + n0 + c] = s + sb[0];
        #pragma unroll
        for (int t = 0; t < 3; t++) {
            float da = 0.0f, db = 0.0f;
            const float* iwt = iw + t*258;
            #pragma unroll 8
            for (int k = 0; k < HH; k++) {
                float hv = s_hT[k][c];
                da += hv * iwt[k];
                db += hv * iwt[128 + k];
            }
            g_dots[t][n0 + c]   = da;
            g_dots[3+t][n0 + c] = db;
        }
    }
    __syncthreads();  // forces consumers done with s_tT

    // conformer: relu(h@ccw1+ccb1) @ ccw2 + ccb2
    b2 = pack2(ccb1[c]);
    #pragma unroll
    for (int q = 0; q < 16; q++) acc[q] = b2;
    gemm_k(acc, s_hT, ccw1, c, HH);
    #pragma unroll
    for (int p2 = 0; p2 < 16; p2++) {
        float2 f = unpack2(acc[p2]);
        s_tT[c][2*p2]   = fmaxf(f.x, 0.0f);
        s_tT[c][2*p2+1] = fmaxf(f.y, 0.0f);
    }
    __syncthreads();
    if (c < 64) {
        ull bb = pack2(ccb2[c]);
        #pragma unroll
        for (int q = 0; q < 16; q++) acc[q] = bb;
        #pragma unroll 4
        for (int k = 0; k < HH; k++) {
            ull w2 = pack2(ccw2[k*64 + c]);
            const ulonglong2* r = reinterpret_cast<const ulonglong2*>(s_tT[k]);
            #pragma unroll
            for (int q = 0; q < 8; q++) {
                ulonglong2 v = r[q];
                ffma2(acc[2*q],   v.x, w2);
                ffma2(acc[2*q+1], v.y, w2);
            }
        }
        #pragma unroll
        for (int p2 = 0; p2 < 16; p2++) {
            float2 f = unpack2(acc[p2]);
            out[OFF_CONF + (n0+2*p2)*64 + c]   = f.x;
            out[OFF_CONF + (n0+2*p2+1)*64 + c] = f.y;
        }
    }
}

// ---------------- interaction scores ----------------
__global__ void scores_kernel(const float* __restrict__ iw, const float* __restrict__ ib,
                              float* __restrict__ out) {
    int idx = blockIdx.x * blockDim.x + threadIdx.x;
    if (idx >= NN*KI) return;
    int i = idx / KI, e = idx % KI;
    const float* p = g_pos[0];
    int cnt = g_icnt[i];
    int j = g_iidx[i*KI + e];
    float mask = (e < cnt) ? 1.0f : 0.0f;
    float dx = p[3*i]-p[3*j], dy = p[3*i+1]-p[3*j+1], dz = p[3*i+2]-p[3*j+2];
    float dist = sqrtf(dx*dx + dy*dy + dz*dz + 1e-12f);
    #pragma unroll
    for (int t = 0; t < 3; t++) {
        const float* iwt = iw + t*258;
        float x = g_dots[t][i] + g_dots[3+t][j]
                + dist*iwt[256] + (dist/10.0f)*iwt[257] + ib[t];
        out[OFF_S + t*(NN*KI) + i*KI + e] = (1.0f/(1.0f + __expf(-x))) * mask;
    }
}

// ---------------- host orchestration ----------------
extern "C" void kernel_launch(void* const* d_in, const int* in_sizes, int n_in,
                              void* d_out, int out_size)
{
    const float* h     = (const float*)d_in[0];
    const float* pos   = (const float*)d_in[1];
    const int*   batch = (const int*)  d_in[2];
    const float* ew1   = (const float*)d_in[3];
    const float* eb1   = (const float*)d_in[4];
    const float* ew2   = (const float*)d_in[5];
    const float* eb2   = (const float*)d_in[6];
    const float* cw1   = (const float*)d_in[7];
    const float* cb1   = (const float*)d_in[8];
    const float* cw2   = (const float*)d_in[9];
    const float* nw1   = (const float*)d_in[10];
    const float* nb1   = (const float*)d_in[11];
    const float* nw2   = (const float*)d_in[12];
    const float* nb2   = (const float*)d_in[13];
    const float* fw1   = (const float*)d_in[14];
    const float* fb1   = (const float*)d_in[15];
    const float* fw2   = (const float*)d_in[16];
    const float* fb2   = (const float*)d_in[17];
    const float* iw    = (const float*)d_in[18];
    const float* ib    = (const float*)d_in[19];
    const float* ccw1  = (const float*)d_in[20];
    const float* ccb1  = (const float*)d_in[21];
    const float* ccw2  = (const float*)d_in[22];
    const float* ccb2  = (const float*)d_in[23];
    const float* sw    = (const float*)d_in[24];
    const float* sb    = (const float*)d_in[25];
    float* out = (float*)d_out;

    seg_kernel<<<1, 64>>>(batch);
    init_copy<<<(NN*HH + 255)/256, 256>>>(h, pos);

    const float cut2[3] = {9.0f, 36.0f, 100.0f};
    int sel = 0;
    for (int l = 0; l < 6; l++) {
        if ((l & 1) == 0)
            neighbors_kernel<KM, false><<<NN/32, 32>>>(sel, batch, cut2[l/2]);
        const float* ew1l = ew1 + l*257*HH;
        pre_kernel<<<NN/TILE, HH>>>(sel, ew1l, eb1 + l*HH);
        edge_kernel<<<NN, HH>>>(sel, ew1l + 256*HH,
                                ew2 + l*HH*HH, eb2 + l*HH,
                                cw1 + l*HH*HH, cb1 + l*HH,
                                cw2 + l*HH);
        node_kernel<<<NN/TILE, HH>>>(sel, nw1 + l*256*HH, nb1 + l*HH,
                                     nw2 + l*HH*HH, nb2 + l*HH);
        sel ^= 1;
    }
    // sel == 0 after 6 layers
    neighbors_kernel<KI, true><<<NN/32, 32>>>(0, batch, 100.0f);
    final_tile_kernel<<<NN/TILE, HH>>>(fw1, fb1, fw2, fb2,
                                       ccw1, ccb1, ccw2, ccb2,
                                       sw, sb, iw, out);
    scores_kernel<<<(NN*KI + 255)/256, 256>>>(iw, ib, out);
}

// round 3
// speedup vs baseline: 1.4092x; 1.0005x over previous
#include <cuda_runtime.h>
#include <math.h>

#define NN 4096
#define HH 128
#define KM 32
#define KI 20
#define BB 32
#define TPAD 36
#define TILE 32

// ---------------- output layout (floats) ----------------
#define OFF_H    0
#define OFF_POS  (NN*HH)
#define OFF_F    (OFF_POS + NN*3)
#define OFF_S    (OFF_F + NN*3)
#define OFF_CONF (OFF_S + 3*NN*KI)
#define OFF_ST   (OFF_CONF + NN*64)

typedef unsigned long long ull;

// ---------------- device scratch ----------------
__device__ float g_h[2][NN*HH];
__device__ float g_pos[2][NN*3];
__device__ float g_A[NN*HH];
__device__ float g_B[NN*HH];
__device__ float g_agg[NN*HH];
__device__ float g_dots[6][NN];
__device__ int   g_idx[NN*KM];
__device__ int   g_cnt[NN];
__device__ int   g_iidx[NN*KI];
__device__ int   g_icnt[NN];
__device__ int   g_seg[BB+1];

__device__ __forceinline__ float silu_f(float x) { return x / (1.0f + __expf(-x)); }

__device__ __forceinline__ ull pack2(float x) {
    ull r;
    asm("mov.b64 %0, {%1, %1};" : "=l"(r) : "r"(__float_as_uint(x)));
    return r;
}
__device__ __forceinline__ void ffma2(ull& a, ull v, ull w) {
    asm("fma.rn.f32x2 %0, %1, %2, %0;" : "+l"(a) : "l"(v), "l"(w));
}
__device__ __forceinline__ float2 unpack2(ull a) {
    unsigned lo, hi;
    asm("mov.b64 {%0, %1}, %2;" : "=r"(lo), "=r"(hi) : "l"(a));
    return make_float2(__uint_as_float(lo), __uint_as_float(hi));
}

// run a packed k-loop over a transposed smem tile: acc[p] covers lanes (2p,2p+1) of 32
__device__ __forceinline__ void gemm_k(ull* acc, const float (*T)[TPAD],
                                       const float* __restrict__ W, int c, int kk) {
    #pragma unroll 4
    for (int k = 0; k < kk; k++) {
        ull w2 = pack2(W[k*HH + c]);
        const ulonglong2* r = reinterpret_cast<const ulonglong2*>(T[k]);
        #pragma unroll
        for (int q = 0; q < 8; q++) {
            ulonglong2 v = r[q];
            ffma2(acc[2*q],   v.x, w2);
            ffma2(acc[2*q+1], v.y, w2);
        }
    }
}

// ---------------- batch segment boundaries ----------------
__global__ void seg_kernel(const int* __restrict__ batch) {
    int b = threadIdx.x;
    if (b <= BB) {
        int lo = 0, hi = NN;
        while (lo < hi) { int mid = (lo + hi) >> 1; if (batch[mid] < b) lo = mid + 1; else hi = mid; }
        g_seg[b] = lo;
    }
}

__global__ void init_copy(const float* __restrict__ h, const float* __restrict__ p) {
    int i = blockIdx.x * blockDim.x + threadIdx.x;
    if (i < NN*HH) g_h[0][i] = h[i];
    if (i < NN*3)  g_pos[0][i] = p[i];
}

// ---------------- radius graph ----------------
template<int KK, bool INTER>
__global__ void neighbors_kernel(int sel, const int* __restrict__ batch, float cutoff2) {
    int i = blockIdx.x * blockDim.x + threadIdx.x;
    if (i >= NN) return;
    const float* p = g_pos[sel];
    int b  = batch[i];
    int s0 = g_seg[b], s1 = g_seg[b+1];
    float px = p[3*i], py = p[3*i+1], pz = p[3*i+2];
    float bd[KK]; int bj[KK]; int m = 0;
    for (int j = s0; j < s1; j++) {
        if (j == i) continue;
        float dx = px - p[3*j], dy = py - p[3*j+1], dz = pz - p[3*j+2];
        float d2 = dx*dx + dy*dy + dz*dz;
        if (d2 > cutoff2) continue;
        if (m < KK) {
            int q = m++;
            while (q > 0 && bd[q-1] > d2) { bd[q] = bd[q-1]; bj[q] = bj[q-1]; q--; }
            bd[q] = d2; bj[q] = j;
        } else if (d2 < bd[KK-1]) {
            int q = KK - 1;
            while (q > 0 && bd[q-1] > d2) { bd[q] = bd[q-1]; bj[q] = bj[q-1]; q--; }
            bd[q] = d2; bj[q] = j;
        }
    }
    int* oi = INTER ? g_iidx : g_idx;
    int* oc = INTER ? g_icnt : g_cnt;
    for (int e = 0; e < KK; e++) oi[i*KK + e] = (e < m) ? bj[e] : i;
    oc[i] = m;
}

// ---------------- per-layer precompute: A = h@W1a + eb1, B = h@W1b ----------------
__global__ __launch_bounds__(HH) void pre_kernel(int sel, const float* __restrict__ ew1,
                                                 const float* __restrict__ eb1) {
    int n0 = blockIdx.x * TILE, c = threadIdx.x;
    const float* h = g_h[sel];
    __shared__ __align__(16) float s_hT[HH][TPAD];
    #pragma unroll
    for (int e = 0; e < TILE; e++) s_hT[c][e] = h[(n0+e)*HH + c];
    __syncthreads();

    ull acc[16];
    ull b2 = pack2(eb1[c]);
    #pragma unroll
    for (int q = 0; q < 16; q++) acc[q] = b2;
    gemm_k(acc, s_hT, ew1, c, HH);
    #pragma unroll
    for (int p = 0; p < 16; p++) {
        float2 f = unpack2(acc[p]);
        g_A[(n0+2*p)*HH + c]   = f.x;
        g_A[(n0+2*p+1)*HH + c] = f.y;
    }
    ull z = pack2(0.0f);
    #pragma unroll
    for (int q = 0; q < 16; q++) acc[q] = z;
    gemm_k(acc, s_hT, ew1 + HH*HH, c, HH);
    #pragma unroll
    for (int p = 0; p < 16; p++) {
        float2 f = unpack2(acc[p]);
        g_B[(n0+2*p)*HH + c]   = f.x;
        g_B[(n0+2*p+1)*HH + c] = f.y;
    }
}

// ---------------- per-edge kernel: m1 -> m (GEMM2) -> coord MLP -> pos update + agg ----------------
__global__ __launch_bounds__(HH, 5) void edge_kernel(
    int sel,
    const float* __restrict__ ew1d,   // d2 weight row (ew1 + 256*HH)
    const float* __restrict__ ew2, const float* __restrict__ eb2,
    const float* __restrict__ cw1, const float* __restrict__ cb1,
    const float* __restrict__ cw2)
{
    const int i = blockIdx.x, c = threadIdx.x;
    const float* p_in = g_pos[sel];
    float* p_out = g_pos[sel^1];

    __shared__ __align__(16) float s_T1[HH][TPAD];
    __shared__ __align__(16) float s_T2[HH][TPAD];
    __shared__ float s_d2[KM], s_rel[3][KM], s_mask[KM], s_cE[KM];
    __shared__ int   s_j[KM];

    if (c < KM) {
        int cnt = g_cnt[i];
        int j = (c < cnt) ? g_idx[i*KM + c] : i;
        s_j[c] = j;
        s_mask[c] = (c < cnt) ? 1.0f : 0.0f;
        float rx = p_in[3*i]   - p_in[3*j];
        float ry = p_in[3*i+1] - p_in[3*j+1];
        float rz = p_in[3*i+2] - p_in[3*j+2];
        s_rel[0][c] = rx; s_rel[1][c] = ry; s_rel[2][c] = rz;
        s_d2[c] = rx*rx + ry*ry + rz*rz;
    }
    __syncthreads();

    // m1T[c][e] = silu(A[i][c] + B[j][c] + d2*wd[c])   (GEMM1 eliminated by linearity)
    {
        float base = g_A[i*HH + c];
        float wd = ew1d[c];
        #pragma unroll
        for (int e = 0; e < KM; e++) {
            float v = g_B[s_j[e]*HH + c];
            s_T1[c][e] = silu_f(fmaf(s_d2[e], wd, base + v));
        }
    }
    __syncthreads();

    ull acc[16];

    // GEMM2: m = silu(m1@ew2 + eb2) * mask ; agg = sum_e m
    {
        ull b2 = pack2(eb2[c]);
        #pragma unroll
        for (int q = 0; q < 16; q++) acc[q] = b2;
        gemm_k(acc, s_T1, ew2, c, HH);
        float aggc = 0.0f;
        #pragma unroll
        for (int p = 0; p < 16; p++) {
            float2 f = unpack2(acc[p]);
            float m0 = silu_f(f.x) * s_mask[2*p];
            float m1 = silu_f(f.y) * s_mask[2*p+1];
            s_T2[c][2*p] = m0; s_T2[c][2*p+1] = m1;
            aggc += m0 + m1;
        }
        g_agg[i*HH + c] = aggc;
    }
    __syncthreads();

    // coord MLP: cE = silu(m@cw1 + cb1) @ cw2
    {
        ull b2 = pack2(cb1[c]);
        #pragma unroll
        for (int q = 0; q < 16; q++) acc[q] = b2;
        gemm_k(acc, s_T2, cw1, c, HH);
        float w2 = cw2[c];
        float* red = &s_T1[0][0];   // reuse as [KM][132]
        #pragma unroll
        for (int p = 0; p < 16; p++) {
            float2 f = unpack2(acc[p]);
            red[(2*p)*132 + c]   = silu_f(f.x) * w2;
            red[(2*p+1)*132 + c] = silu_f(f.y) * w2;
        }
    }
    __syncthreads();
    if (c < KM) {
        const float* red = &s_T1[0][0];
        float s = 0.0f;
        #pragma unroll 8
        for (int k = 0; k < HH; k++) s += red[c*132 + k];
        s_cE[c] = s;
    }
    __syncthreads();
    if (c < 3) {
        float dp = 0.0f;
        #pragma unroll
        for (int e = 0; e < KM; e++) dp += s_rel[c][e] * s_cE[e] * s_mask[e];
        float cntf = fmaxf((float)g_cnt[i], 1.0f);
        p_out[3*i + c] = p_in[3*i + c] + dp / cntf;
    }
}

// ---------------- node MLP (tiled): h_out = h + silu([h|agg]@nw1+nb1)@nw2+nb2 ----------------
__global__ __launch_bounds__(HH) void node_kernel(
    int sel,
    const float* __restrict__ nw1, const float* __restrict__ nb1,
    const float* __restrict__ nw2, const float* __restrict__ nb2)
{
    int n0 = blockIdx.x * TILE, c = threadIdx.x;
    const float* h_in = g_h[sel];
    float* h_out = g_h[sel^1];
    __shared__ __align__(16) float s_hT[HH][TPAD];
    __shared__ __align__(16) float s_aT[HH][TPAD];
    #pragma unroll
    for (int e = 0; e < TILE; e++) s_hT[c][e] = h_in[(n0+e)*HH + c];
    #pragma unroll
    for (int e = 0; e < TILE; e++) s_aT[c][e] = g_agg[(n0+e)*HH + c];
    __syncthreads();

    ull acc[16];
    ull b2 = pack2(nb1[c]);
    #pragma unroll
    for (int q = 0; q < 16; q++) acc[q] = b2;
    gemm_k(acc, s_hT, nw1, c, HH);
    gemm_k(acc, s_aT, nw1 + HH*HH, c, HH);
    __syncthreads();             // everyone done reading s_aT
    #pragma unroll
    for (int p = 0; p < 16; p++) {
        float2 f = unpack2(acc[p]);
        s_aT[c][2*p]   = silu_f(f.x);
        s_aT[c][2*p+1] = silu_f(f.y);
    }
    __syncthreads();

    b2 = pack2(nb2[c]);
    #pragma unroll
    for (int q = 0; q < 16; q++) acc[q] = b2;
    gemm_k(acc, s_aT, nw2, c, HH);
    #pragma unroll
    for (int p = 0; p < 16; p++) {
        float2 f = unpack2(acc[p]);
        h_out[(n0+2*p)*HH + c]   = s_hT[c][2*p]   + f.x;
        h_out[(n0+2*p+1)*HH + c] = s_hT[c][2*p+1] + f.y;
    }
}

// ---------------- final per-node-tile readout: forces/conformer/steric/dots + h,pos copy ----------------
__global__ __launch_bounds__(HH) void final_tile_kernel(
    const float* __restrict__ fw1, const float* __restrict__ fb1,
    const float* __restrict__ fw2, const float* __restrict__ fb2,
    const float* __restrict__ ccw1, const float* __restrict__ ccb1,
    const float* __restrict__ ccw2, const float* __restrict__ ccb2,
    const float* __restrict__ sw,  const float* __restrict__ sb,
    const float* __restrict__ iw,
    float* __restrict__ out)
{
    int n0 = blockIdx.x * TILE, c = threadIdx.x;
    const float* h = g_h[0];
    const float* p = g_pos[0];
    __shared__ __align__(16) float s_hT[HH][TPAD];
    __shared__ __align__(16) float s_tT[HH][TPAD];

    #pragma unroll
    for (int e = 0; e < TILE; e++) {
        float v = h[(n0+e)*HH + c];
        s_hT[c][e] = v;
        out[OFF_H + (n0+e)*HH + c] = v;
    }
    if (c < 3) {
        for (int e = 0; e < TILE; e++)
            out[OFF_POS + (n0+e)*3 + c] = p[(n0+e)*3 + c];
    }
    __syncthreads();

    ull acc[16];

    // forces hidden: tanh(h@fw1 + fb1)
    ull b2 = pack2(fb1[c]);
    #pragma unroll
    for (int q = 0; q < 16; q++) acc[q] = b2;
    gemm_k(acc, s_hT, fw1, c, HH);
    #pragma unroll
    for (int p2 = 0; p2 < 16; p2++) {
        float2 f = unpack2(acc[p2]);
        s_tT[c][2*p2]   = tanhf(f.x);
        s_tT[c][2*p2+1] = tanhf(f.y);
    }
    __syncthreads();
    if (c < 96) {
        int e = c / 3, t = c % 3;
        float s = 0.0f;
        #pragma unroll 8
        for (int k = 0; k < HH; k++) s += s_tT[k][e] * fw2[k*3 + t];
        out[OFF_F + (n0+e)*3 + t] = s + fb2[t];
    }

    // steric + interaction dots (per node reductions over s_hT columns)
    if (c < TILE) {
        float s = 0.0f;
        #pragma unroll 8
        for (int k = 0; k < HH; k++) s += s_hT[k][c] * sw[k];
        out[OFF_ST + n0 + c] = s + sb[0];
        #pragma unroll
        for (int t = 0; t < 3; t++) {
            float da = 0.0f, db = 0.0f;
            const float* iwt = iw + t*258;
            #pragma unroll 8
            for (int k = 0; k < HH; k++) {
                float hv = s_hT[k][c];
                da += hv * iwt[k];
                db += hv * iwt[128 + k];
            }
            g_dots[t][n0 + c]   = da;
            g_dots[3+t][n0 + c] = db;
        }
    }
    __syncthreads();  // forces consumers done with s_tT

    // conformer: relu(h@ccw1+ccb1) @ ccw2 + ccb2
    b2 = pack2(ccb1[c]);
    #pragma unroll
    for (int q = 0; q < 16; q++) acc[q] = b2;
    gemm_k(acc, s_hT, ccw1, c, HH);
    #pragma unroll
    for (int p2 = 0; p2 < 16; p2++) {
        float2 f = unpack2(acc[p2]);
        s_tT[c][2*p2]   = fmaxf(f.x, 0.0f);
        s_tT[c][2*p2+1] = fmaxf(f.y, 0.0f);
    }
    __syncthreads();
    if (c < 64) {
        ull bb = pack2(ccb2[c]);
        #pragma unroll
        for (int q = 0; q < 16; q++) acc[q] = bb;
        #pragma unroll 4
        for (int k = 0; k < HH; k++) {
            ull w2 = pack2(ccw2[k*64 + c]);
            const ulonglong2* r = reinterpret_cast<const ulonglong2*>(s_tT[k]);
            #pragma unroll
            for (int q = 0; q < 8; q++) {
                ulonglong2 v = r[q];
                ffma2(acc[2*q],   v.x, w2);
                ffma2(acc[2*q+1], v.y, w2);
            }
        }
        #pragma unroll
        for (int p2 = 0; p2 < 16; p2++) {
            float2 f = unpack2(acc[p2]);
            out[OFF_CONF + (n0+2*p2)*64 + c]   = f.x;
            out[OFF_CONF + (n0+2*p2+1)*64 + c] = f.y;
        }
    }
}

// ---------------- interaction scores ----------------
__global__ void scores_kernel(const float* __restrict__ iw, const float* __restrict__ ib,
                              float* __restrict__ out) {
    int idx = blockIdx.x * blockDim.x + threadIdx.x;
    if (idx >= NN*KI) return;
    int i = idx / KI, e = idx % KI;
    const float* p = g_pos[0];
    int cnt = g_icnt[i];
    int j = g_iidx[i*KI + e];
    float mask = (e < cnt) ? 1.0f : 0.0f;
    float dx = p[3*i]-p[3*j], dy = p[3*i+1]-p[3*j+1], dz = p[3*i+2]-p[3*j+2];
    float dist = sqrtf(dx*dx + dy*dy + dz*dz + 1e-12f);
    #pragma unroll
    for (int t = 0; t < 3; t++) {
        const float* iwt = iw + t*258;
        float x = g_dots[t][i] + g_dots[3+t][j]
                + dist*iwt[256] + (dist/10.0f)*iwt[257] + ib[t];
        out[OFF_S + t*(NN*KI) + i*KI + e] = (1.0f/(1.0f + __expf(-x))) * mask;
    }
}

// ---------------- host orchestration ----------------
extern "C" void kernel_launch(void* const* d_in, const int* in_sizes, int n_in,
                              void* d_out, int out_size)
{
    const float* h     = (const float*)d_in[0];
    const float* pos   = (const float*)d_in[1];
    const int*   batch = (const int*)  d_in[2];
    const float* ew1   = (const float*)d_in[3];
    const float* eb1   = (const float*)d_in[4];
    const float* ew2   = (const float*)d_in[5];
    const float* eb2   = (const float*)d_in[6];
    const float* cw1   = (const float*)d_in[7];
    const float* cb1   = (const float*)d_in[8];
    const float* cw2   = (const float*)d_in[9];
    const float* nw1   = (const float*)d_in[10];
    const float* nb1   = (const float*)d_in[11];
    const float* nw2   = (const float*)d_in[12];
    const float* nb2   = (const float*)d_in[13];
    const float* fw1   = (const float*)d_in[14];
    const float* fb1   = (const float*)d_in[15];
    const float* fw2   = (const float*)d_in[16];
    const float* fb2   = (const float*)d_in[17];
    const float* iw    = (const float*)d_in[18];
    const float* ib    = (const float*)d_in[19];
    const float* ccw1  = (const float*)d_in[20];
    const float* ccb1  = (const float*)d_in[21];
    const float* ccw2  = (const float*)d_in[22];
    const float* ccb2  = (const float*)d_in[23];
    const float* sw    = (const float*)d_in[24];
    const float* sb    = (const float*)d_in[25];
    float* out = (float*)d_out;

    seg_kernel<<<1, 64>>>(batch);
    init_copy<<<(NN*HH + 255)/256, 256>>>(h, pos);

    const float cut2[3] = {9.0f, 36.0f, 100.0f};
    int sel = 0;
    for (int l = 0; l < 6; l++) {
        if ((l & 1) == 0)
            neighbors_kernel<KM, false><<<NN/32, 32>>>(sel, batch, cut2[l/2]);
        const float* ew1l = ew1 + l*257*HH;
        pre_kernel<<<NN/TILE, HH>>>(sel, ew1l, eb1 + l*HH);
        edge_kernel<<<NN, HH>>>(sel, ew1l + 256*HH,
                                ew2 + l*HH*HH, eb2 + l*HH,
                                cw1 + l*HH*HH, cb1 + l*HH,
                                cw2 + l*HH);
        node_kernel<<<NN/TILE, HH>>>(sel, nw1 + l*256*HH, nb1 + l*HH,
                                     nw2 + l*HH*HH, nb2 + l*HH);
        sel ^= 1;
    }
    // sel == 0 after 6 layers
    neighbors_kernel<KI, true><<<NN/32, 32>>>(0, batch, 100.0f);
    final_tile_kernel<<<NN/TILE, HH>>>(fw1, fb1, fw2, fb2,
                                       ccw1, ccb1, ccw2, ccb2,
                                       sw, sb, iw, out);
    scores_kernel<<<(NN*KI + 255)/256, 256>>>(iw, ib, out);
}

// round 7
// speedup vs baseline: 2.0086x; 1.4253x over previous
#include <cuda_runtime.h>
#include <cuda_bf16.h>
#include <cstdint>
#include <math.h>

#define NN 4096
#define HH 128
#define KM 32
#define KI 20
#define BB 32
#define SMP 132   // smem row pitch (floats) for staged m

#define OFF_H    0
#define OFF_POS  (NN*HH)
#define OFF_F    (OFF_POS + NN*3)
#define OFF_S    (OFF_F + NN*3)
#define OFF_CONF (OFF_S + 3*NN*KI)
#define OFF_ST   (OFF_CONF + NN*64)

typedef unsigned long long ull;

__device__ float g_h[2][NN*HH];
__device__ float g_pos[2][NN*3];
__device__ float g_A[NN*HH];
__device__ float g_B[NN*HH];
__device__ float g_agg[NN*HH];
__device__ float g_dots[6][NN];
__device__ int   g_idx[NN*KM];
__device__ int   g_cnt[NN];
__device__ int   g_iidx[NN*KI];
__device__ int   g_icnt[NN];
__device__ int   g_seg[BB+1];
// fragment-packed bf16 weights: [l][mat(2)][part(3)][4096] uint2
__device__ __align__(16) uint2 g_Wfrag[36*4096];

__device__ __forceinline__ float silu_f(float x) {
    return __fdividef(x, 1.0f + __expf(-x));
}

// ---- packed fp32x2 scalar GEMM helpers ----
__device__ __forceinline__ ull pack2(float x) {
    ull r; asm("mov.b64 %0, {%1, %1};" : "=l"(r) : "r"(__float_as_uint(x))); return r;
}
__device__ __forceinline__ void ffma2(ull& a, ull v, ull w) {
    asm("fma.rn.f32x2 %0, %1, %2, %0;" : "+l"(a) : "l"(v), "l"(w));
}
__device__ __forceinline__ float2 unpack2(ull a) {
    unsigned lo, hi; asm("mov.b64 {%0, %1}, %2;" : "=r"(lo), "=r"(hi) : "l"(a));
    return make_float2(__uint_as_float(lo), __uint_as_float(hi));
}
template<int NE2, int TP>
__device__ __forceinline__ void gemm_t(ull* acc, const float (*T)[TP],
                                       const float* __restrict__ W, int c, int kk) {
    #pragma unroll 4
    for (int k = 0; k < kk; k++) {
        ull w2 = pack2(W[k*HH + c]);
        const ulonglong2* r = reinterpret_cast<const ulonglong2*>(T[k]);
        #pragma unroll
        for (int q = 0; q < NE2; q++) {
            ulonglong2 v = r[q];
            ffma2(acc[2*q], v.x, w2); ffma2(acc[2*q+1], v.y, w2);
        }
    }
}

// ---- mma.sync helpers ----
__device__ __forceinline__ void mma_bf16(float* d, const uint32_t* a, uint2 b) {
    asm volatile("mma.sync.aligned.m16n8k16.row.col.f32.bf16.bf16.f32 "
        "{%0,%1,%2,%3}, {%4,%5,%6,%7}, {%8,%9}, {%0,%1,%2,%3};"
        : "+f"(d[0]), "+f"(d[1]), "+f"(d[2]), "+f"(d[3])
        : "r"(a[0]), "r"(a[1]), "r"(a[2]), "r"(a[3]), "r"(b.x), "r"(b.y));
}
// 3-way bf16 split of a packed pair
__device__ __forceinline__ void split3x2(float x, float y,
                                         uint32_t& u0, uint32_t& u1, uint32_t& u2) {
    __nv_bfloat162 v0 = __floats2bfloat162_rn(x, y);
    float rx = x - __bfloat162float(v0.x), ry = y - __bfloat162float(v0.y);
    __nv_bfloat162 v1 = __floats2bfloat162_rn(rx, ry);
    rx -= __bfloat162float(v1.x); ry -= __bfloat162float(v1.y);
    __nv_bfloat162 v2 = __floats2bfloat162_rn(rx, ry);
    u0 = *reinterpret_cast<uint32_t*>(&v0);
    u1 = *reinterpret_cast<uint32_t*>(&v1);
    u2 = *reinterpret_cast<uint32_t*>(&v2);
}
__device__ __forceinline__ __nv_bfloat16 wpart3(float w, int part) {
    __nv_bfloat16 p0 = __float2bfloat16(w);
    if (part == 0) return p0;
    float r = w - __bfloat162float(p0);
    __nv_bfloat16 p1 = __float2bfloat16(r);
    if (part == 1) return p1;
    return __float2bfloat16(r - __bfloat162float(p1));
}
// 6-term 3-way-split GEMM for one k-step over 16 n-tiles
__device__ __forceinline__ void gemm6(float (*acc)[4],
                                      const uint32_t* a0, const uint32_t* a1, const uint32_t* a2,
                                      const uint2* __restrict__ p0, const uint2* __restrict__ p1,
                                      const uint2* __restrict__ p2) {
    #pragma unroll
    for (int nt = 0; nt < 16; nt++) mma_bf16(acc[nt], a0, __ldg(p0 + nt*32));
    #pragma unroll
    for (int nt = 0; nt < 16; nt++) mma_bf16(acc[nt], a0, __ldg(p1 + nt*32));
    #pragma unroll
    for (int nt = 0; nt < 16; nt++) mma_bf16(acc[nt], a1, __ldg(p0 + nt*32));
    #pragma unroll
    for (int nt = 0; nt < 16; nt++) mma_bf16(acc[nt], a0, __ldg(p2 + nt*32));
    #pragma unroll
    for (int nt = 0; nt < 16; nt++) mma_bf16(acc[nt], a1, __ldg(p1 + nt*32));
    #pragma unroll
    for (int nt = 0; nt < 16; nt++) mma_bf16(acc[nt], a2, __ldg(p0 + nt*32));
}

// ---- weight prep: pack W[k][n] into mma B-fragment order, 3 parts ----
__global__ void wprep_kernel(const float* __restrict__ ew2, const float* __restrict__ cw1) {
    int b = blockIdx.x;            // b = l*6 + mat*3 + part
    int l = b / 6, mat = (b / 3) % 2, part = b % 3;
    const float* W = (mat ? cw1 : ew2) + l * HH * HH;
    uint2* dst = g_Wfrag + b * 4096;
    for (int idx = threadIdx.x; idx < 4096; idx += blockDim.x) {
        int fg = idx >> 5, lane = idx & 31;
        int ks = fg >> 4, nt = fg & 15, quad = lane >> 2, qt = lane & 3;
        int k0 = ks*16 + qt*2, n = nt*8 + quad;
        __nv_bfloat162 v0, v1;
        v0.x = wpart3(W[k0*HH + n], part);     v0.y = wpart3(W[(k0+1)*HH + n], part);
        v1.x = wpart3(W[(k0+8)*HH + n], part); v1.y = wpart3(W[(k0+9)*HH + n], part);
        uint2 u;
        u.x = *reinterpret_cast<uint32_t*>(&v0);
        u.y = *reinterpret_cast<uint32_t*>(&v1);
        dst[idx] = u;
    }
}

__global__ void seg_kernel(const int* __restrict__ batch) {
    int b = threadIdx.x;
    if (b <= BB) {
        int lo = 0, hi = NN;
        while (lo < hi) { int mid = (lo + hi) >> 1; if (batch[mid] < b) lo = mid + 1; else hi = mid; }
        g_seg[b] = lo;
    }
}
__global__ void init_copy(const float* __restrict__ h, const float* __restrict__ p) {
    int i = blockIdx.x * blockDim.x + threadIdx.x;
    if (i < NN*HH) g_h[0][i] = h[i];
    if (i < NN*3)  g_pos[0][i] = p[i];
}

template<int KK, bool INTER>
__global__ void neighbors_kernel(int sel, const int* __restrict__ batch, float cutoff2) {
    int i = blockIdx.x * blockDim.x + threadIdx.x;
    if (i >= NN) return;
    const float* p = g_pos[sel];
    int b = batch[i];
    int s0 = g_seg[b], s1 = g_seg[b+1];
    float px = p[3*i], py = p[3*i+1], pz = p[3*i+2];
    float bd[KK]; int bj[KK]; int m = 0;
    for (int j = s0; j < s1; j++) {
        if (j == i) continue;
        float dx = px - p[3*j], dy = py - p[3*j+1], dz = pz - p[3*j+2];
        float d2 = dx*dx + dy*dy + dz*dz;
        if (d2 > cutoff2) continue;
        if (m < KK) {
            int q = m++;
            while (q > 0 && bd[q-1] > d2) { bd[q] = bd[q-1]; bj[q] = bj[q-1]; q--; }
            bd[q] = d2; bj[q] = j;
        } else if (d2 < bd[KK-1]) {
            int q = KK - 1;
            while (q > 0 && bd[q-1] > d2) { bd[q] = bd[q-1]; bj[q] = bj[q-1]; q--; }
            bd[q] = d2; bj[q] = j;
        }
    }
    int* oi = INTER ? g_iidx : g_idx;
    int* oc = INTER ? g_icnt : g_cnt;
    for (int e = 0; e < KK; e++) oi[i*KK + e] = (e < m) ? bj[e] : i;
    oc[i] = m;
}

// ---- pre: A = h@ew1a + eb1 (wg0), B = h@ew1b (wg1); grid 512 ----
__global__ __launch_bounds__(256) void pre_kernel(int sel, const float* __restrict__ ew1,
                                                  const float* __restrict__ eb1) {
    int n0 = blockIdx.x * 8;
    int c = threadIdx.x & 127, wg = threadIdx.x >> 7;
    const float* h = g_h[sel];
    __shared__ __align__(16) float s_hT[HH][12];
    #pragma unroll
    for (int e = 0; e < 4; e++) s_hT[c][wg*4 + e] = h[(n0 + wg*4 + e)*HH + c];
    __syncthreads();
    ull acc[4];
    ull b2 = wg ? pack2(0.0f) : pack2(eb1[c]);
    #pragma unroll
    for (int q = 0; q < 4; q++) acc[q] = b2;
    gemm_t<2,12>(acc, s_hT, ew1 + wg*HH*HH, c, HH);
    float* outp = wg ? g_B : g_A;
    #pragma unroll
    for (int p = 0; p < 4; p++) {
        float2 f = unpack2(acc[p]);
        outp[(n0+2*p)*HH + c] = f.x; outp[(n0+2*p+1)*HH + c] = f.y;
    }
}

// ---- edge kernel: 4 nodes (128 edge-rows) per CTA, HMMA 3-way-split ----
#define EDGE_DSM (128*SMP*4)

__global__ __launch_bounds__(256) void edge_mma_kernel(
    int sel, int layer,
    const float* __restrict__ ew1d, const float* __restrict__ eb2,
    const float* __restrict__ cb1,  const float* __restrict__ cw2)
{
    extern __shared__ float sM[];   // [128][SMP] staged m (fp32)
    __shared__ int   sJ[128];
    __shared__ float sMask[128], sD2[128], sRel[3*128];
    __shared__ float sWD[128], sEB2[128], sCB1[128], sCW2[128];
    __shared__ float sAgg[8][128];
    __shared__ float sCE[128];

    const int blk = blockIdx.x, tid = threadIdx.x;
    const int w = tid >> 5, lane = tid & 31, quad = lane >> 2, qt = lane & 3;
    const float* p_in = g_pos[sel];
    float* p_out = g_pos[sel^1];

    if (tid < 128) {
        int n = tid >> 5, e = tid & 31, i = 4*blk + n;
        int cnt = g_cnt[i];
        int j = (e < cnt) ? g_idx[i*KM + e] : i;
        sJ[tid] = j;
        sMask[tid] = (e < cnt) ? 1.0f : 0.0f;
        float rx = p_in[3*i] - p_in[3*j], ry = p_in[3*i+1] - p_in[3*j+1], rz = p_in[3*i+2] - p_in[3*j+2];
        sRel[tid] = rx; sRel[128+tid] = ry; sRel[256+tid] = rz;
        sD2[tid] = rx*rx + ry*ry + rz*rz;
        sWD[tid] = ew1d[tid]; sEB2[tid] = eb2[tid]; sCB1[tid] = cb1[tid]; sCW2[tid] = cw2[tid];
    }
    __syncthreads();

    const int iNode = 4*blk + (w >> 1);
    const int r0 = 16*w + quad, r1 = r0 + 8;
    const int j0 = sJ[r0], j1 = sJ[r1];
    const float d20 = sD2[r0], d21 = sD2[r1];
    const float mk0 = sMask[r0], mk1 = sMask[r1];
    const float* gAi = g_A + (size_t)iNode*HH;
    const float* gB0 = g_B + (size_t)j0*HH;
    const float* gB1 = g_B + (size_t)j1*HH;

    const uint2* W1p0 = g_Wfrag + (layer*6 + 0)*4096 + lane;
    const uint2* W1p1 = g_Wfrag + (layer*6 + 1)*4096 + lane;
    const uint2* W1p2 = g_Wfrag + (layer*6 + 2)*4096 + lane;
    const uint2* W2p0 = g_Wfrag + (layer*6 + 3)*4096 + lane;
    const uint2* W2p1 = g_Wfrag + (layer*6 + 4)*4096 + lane;
    const uint2* W2p2 = g_Wfrag + (layer*6 + 5)*4096 + lane;

    float acc[16][4];
    #pragma unroll
    for (int nt = 0; nt < 16; nt++) { acc[nt][0]=0.f; acc[nt][1]=0.f; acc[nt][2]=0.f; acc[nt][3]=0.f; }

    // ---- GEMM1: m1 @ ew2, A frags built on the fly (3-way split) ----
    #pragma unroll
    for (int ks = 0; ks < 8; ks++) {
        int base = ks*16 + qt*2;
        float2 A0 = *reinterpret_cast<const float2*>(gAi + base);
        float2 A8 = *reinterpret_cast<const float2*>(gAi + base + 8);
        float2 B00 = *reinterpret_cast<const float2*>(gB0 + base);
        float2 B08 = *reinterpret_cast<const float2*>(gB0 + base + 8);
        float2 B10 = *reinterpret_cast<const float2*>(gB1 + base);
        float2 B18 = *reinterpret_cast<const float2*>(gB1 + base + 8);
        float2 w0 = *reinterpret_cast<const float2*>(sWD + base);
        float2 w8 = *reinterpret_cast<const float2*>(sWD + base + 8);
        uint32_t a0[4], a1[4], a2[4];
        split3x2(silu_f(fmaf(d20, w0.x, A0.x + B00.x)), silu_f(fmaf(d20, w0.y, A0.y + B00.y)), a0[0], a1[0], a2[0]);
        split3x2(silu_f(fmaf(d21, w0.x, A0.x + B10.x)), silu_f(fmaf(d21, w0.y, A0.y + B10.y)), a0[1], a1[1], a2[1]);
        split3x2(silu_f(fmaf(d20, w8.x, A8.x + B08.x)), silu_f(fmaf(d20, w8.y, A8.y + B08.y)), a0[2], a1[2], a2[2]);
        split3x2(silu_f(fmaf(d21, w8.x, A8.x + B18.x)), silu_f(fmaf(d21, w8.y, A8.y + B18.y)), a0[3], a1[3], a2[3]);
        gemm6(acc, a0, a1, a2, W1p0 + ks*512, W1p1 + ks*512, W1p2 + ks*512);
    }

    // ---- epilogue1: m = silu(D1+eb2)*mask -> sM (fp32, same-thread reuse) + agg ----
    #pragma unroll
    for (int nt = 0; nt < 16; nt++) {
        int cc = nt*8 + qt*2;
        float m00 = silu_f(acc[nt][0] + sEB2[cc])   * mk0;
        float m01 = silu_f(acc[nt][1] + sEB2[cc+1]) * mk0;
        float m10 = silu_f(acc[nt][2] + sEB2[cc])   * mk1;
        float m11 = silu_f(acc[nt][3] + sEB2[cc+1]) * mk1;
        sM[r0*SMP + cc]   = m00; sM[r0*SMP + cc+1] = m01;
        sM[r1*SMP + cc]   = m10; sM[r1*SMP + cc+1] = m11;
        float s0 = m00 + m10, s1 = m01 + m11;
        #pragma unroll
        for (int off = 4; off <= 16; off <<= 1) {
            s0 += __shfl_xor_sync(0xffffffffu, s0, off);
            s1 += __shfl_xor_sync(0xffffffffu, s1, off);
        }
        if (quad == 0) { sAgg[w][cc] = s0; sAgg[w][cc+1] = s1; }
        acc[nt][0] = 0.f; acc[nt][1] = 0.f; acc[nt][2] = 0.f; acc[nt][3] = 0.f;
    }

    // ---- GEMM2: m @ cw1 (A re-split from sM, same-thread data) ----
    #pragma unroll
    for (int ks = 0; ks < 8; ks++) {
        int k0 = ks*16 + qt*2;
        float2 x00 = *reinterpret_cast<const float2*>(sM + r0*SMP + k0);
        float2 x10 = *reinterpret_cast<const float2*>(sM + r1*SMP + k0);
        float2 x08 = *reinterpret_cast<const float2*>(sM + r0*SMP + k0 + 8);
        float2 x18 = *reinterpret_cast<const float2*>(sM + r1*SMP + k0 + 8);
        uint32_t a0[4], a1[4], a2[4];
        split3x2(x00.x, x00.y, a0[0], a1[0], a2[0]);
        split3x2(x10.x, x10.y, a0[1], a1[1], a2[1]);
        split3x2(x08.x, x08.y, a0[2], a1[2], a2[2]);
        split3x2(x18.x, x18.y, a0[3], a1[3], a2[3]);
        gemm6(acc, a0, a1, a2, W2p0 + ks*512, W2p1 + ks*512, W2p2 + ks*512);
    }

    // ---- epilogue2: per-edge coord scalar cE = sum_c silu(D2+cb1)*cw2 ----
    float p0 = 0.f, p1 = 0.f;
    #pragma unroll
    for (int nt = 0; nt < 16; nt++) {
        int cc = nt*8 + qt*2;
        p0 += silu_f(acc[nt][0] + sCB1[cc])*sCW2[cc] + silu_f(acc[nt][1] + sCB1[cc+1])*sCW2[cc+1];
        p1 += silu_f(acc[nt][2] + sCB1[cc])*sCW2[cc] + silu_f(acc[nt][3] + sCB1[cc+1])*sCW2[cc+1];
    }
    p0 += __shfl_xor_sync(0xffffffffu, p0, 1); p0 += __shfl_xor_sync(0xffffffffu, p0, 2);
    p1 += __shfl_xor_sync(0xffffffffu, p1, 1); p1 += __shfl_xor_sync(0xffffffffu, p1, 2);
    if (qt == 0) { sCE[r0] = p0; sCE[r1] = p1; }
    __syncthreads();

    // agg combine
    #pragma unroll
    for (int rep = 0; rep < 2; rep++) {
        int idx = tid + 256*rep;
        int n = idx >> 7, c = idx & 127;
        g_agg[(4*blk + n)*HH + c] = sAgg[2*n][c] + sAgg[2*n+1][c];
    }

    // coord update
    if (w < 4) {
        int r = 32*w + lane, i = 4*blk + w;
        float ce = sCE[r], mk = sMask[r];
        float fx = sRel[r]*ce*mk, fy = sRel[128+r]*ce*mk, fz = sRel[256+r]*ce*mk;
        #pragma unroll
        for (int o = 16; o > 0; o >>= 1) {
            fx += __shfl_down_sync(0xffffffffu, fx, o);
            fy += __shfl_down_sync(0xffffffffu, fy, o);
            fz += __shfl_down_sync(0xffffffffu, fz, o);
        }
        if (lane == 0) {
            float cnt = fmaxf((float)g_cnt[i], 1.0f);
            p_out[3*i+0] = p_in[3*i+0] + fx / cnt;
            p_out[3*i+1] = p_in[3*i+1] + fy / cnt;
            p_out[3*i+2] = p_in[3*i+2] + fz / cnt;
        }
    }
}

// ---- node MLP: TILE=8, grid=512 ----
__global__ __launch_bounds__(HH) void node_kernel(
    int sel,
    const float* __restrict__ nw1, const float* __restrict__ nb1,
    const float* __restrict__ nw2, const float* __restrict__ nb2)
{
    int n0 = blockIdx.x * 8, c = threadIdx.x;
    const float* h_in = g_h[sel];
    float* h_out = g_h[sel^1];
    __shared__ __align__(16) float s_hT[HH][12];
    __shared__ __align__(16) float s_aT[HH][12];
    #pragma unroll
    for (int e = 0; e < 8; e++) s_hT[c][e] = h_in[(n0+e)*HH + c];
    #pragma unroll
    for (int e = 0; e < 8; e++) s_aT[c][e] = g_agg[(n0+e)*HH + c];
    __syncthreads();

    ull acc[4];
    ull b2 = pack2(nb1[c]);
    #pragma unroll
    for (int q = 0; q < 4; q++) acc[q] = b2;
    gemm_t<2,12>(acc, s_hT, nw1, c, HH);
    gemm_t<2,12>(acc, s_aT, nw1 + HH*HH, c, HH);
    __syncthreads();
    #pragma unroll
    for (int p = 0; p < 4; p++) {
        float2 f = unpack2(acc[p]);
        s_aT[c][2*p] = silu_f(f.x); s_aT[c][2*p+1] = silu_f(f.y);
    }
    __syncthreads();
    b2 = pack2(nb2[c]);
    #pragma unroll
    for (int q = 0; q < 4; q++) acc[q] = b2;
    gemm_t<2,12>(acc, s_aT, nw2, c, HH);
    #pragma unroll
    for (int p = 0; p < 4; p++) {
        float2 f = unpack2(acc[p]);
        h_out[(n0+2*p)*HH + c]   = s_hT[c][2*p]   + f.x;
        h_out[(n0+2*p+1)*HH + c] = s_hT[c][2*p+1] + f.y;
    }
}

// ---- final readout (TILE=32) ----
__global__ __launch_bounds__(HH) void final_tile_kernel(
    const float* __restrict__ fw1, const float* __restrict__ fb1,
    const float* __restrict__ fw2, const float* __restrict__ fb2,
    const float* __restrict__ ccw1, const float* __restrict__ ccb1,
    const float* __restrict__ ccw2, const float* __restrict__ ccb2,
    const float* __restrict__ sw,  const float* __restrict__ sb,
    const float* __restrict__ iw,
    float* __restrict__ out)
{
    int n0 = blockIdx.x * 32, c = threadIdx.x;
    const float* h = g_h[0];
    const float* p = g_pos[0];
    __shared__ __align__(16) float s_hT[HH][36];
    __shared__ __align__(16) float s_tT[HH][36];

    #pragma unroll
    for (int e = 0; e < 32; e++) {
        float v = h[(n0+e)*HH + c];
        s_hT[c][e] = v;
        out[OFF_H + (n0+e)*HH + c] = v;
    }
    if (c < 3)
        for (int e = 0; e < 32; e++) out[OFF_POS + (n0+e)*3 + c] = p[(n0+e)*3 + c];
    __syncthreads();

    ull acc[16];
    ull b2 = pack2(fb1[c]);
    #pragma unroll
    for (int q = 0; q < 16; q++) acc[q] = b2;
    gemm_t<8,36>(acc, s_hT, fw1, c, HH);
    #pragma unroll
    for (int p2 = 0; p2 < 16; p2++) {
        float2 f = unpack2(acc[p2]);
        s_tT[c][2*p2] = tanhf(f.x); s_tT[c][2*p2+1] = tanhf(f.y);
    }
    __syncthreads();
    if (c < 96) {
        int e = c / 3, t = c % 3;
        float s = 0.0f;
        #pragma unroll 8
        for (int k = 0; k < HH; k++) s += s_tT[k][e] * fw2[k*3 + t];
        out[OFF_F + (n0+e)*3 + t] = s + fb2[t];
    }
    if (c < 32) {
        float s = 0.0f;
        #pragma unroll 8
        for (int k = 0; k < HH; k++) s += s_hT[k][c] * sw[k];
        out[OFF_ST + n0 + c] = s + sb[0];
        #pragma unroll
        for (int t = 0; t < 3; t++) {
            float da = 0.0f, db = 0.0f;
            const float* iwt = iw + t*258;
            #pragma unroll 8
            for (int k = 0; k < HH; k++) {
                float hv = s_hT[k][c];
                da += hv * iwt[k]; db += hv * iwt[128 + k];
            }
            g_dots[t][n0 + c] = da; g_dots[3+t][n0 + c] = db;
        }
    }
    __syncthreads();

    b2 = pack2(ccb1[c]);
    #pragma unroll
    for (int q = 0; q < 16; q++) acc[q] = b2;
    gemm_t<8,36>(acc, s_hT, ccw1, c, HH);
    #pragma unroll
    for (int p2 = 0; p2 < 16; p2++) {
        float2 f = unpack2(acc[p2]);
        s_tT[c][2*p2] = fmaxf(f.x, 0.0f); s_tT[c][2*p2+1] = fmaxf(f.y, 0.0f);
    }
    __syncthreads();
    if (c < 64) {
        ull bb = pack2(ccb2[c]);
        #pragma unroll
        for (int q = 0; q < 16; q++) acc[q] = bb;
        #pragma unroll 4
        for (int k = 0; k < HH; k++) {
            ull w2 = pack2(ccw2[k*64 + c]);
            const ulonglong2* r = reinterpret_cast<const ulonglong2*>(s_tT[k]);
            #pragma unroll
            for (int q = 0; q < 8; q++) {
                ulonglong2 v = r[q];
                ffma2(acc[2*q], v.x, w2); ffma2(acc[2*q+1], v.y, w2);
            }
        }
        #pragma unroll
        for (int p2 = 0; p2 < 16; p2++) {
            float2 f = unpack2(acc[p2]);
            out[OFF_CONF + (n0+2*p2)*64 + c]   = f.x;
            out[OFF_CONF + (n0+2*p2+1)*64 + c] = f.y;
        }
    }
}

__global__ void scores_kernel(const float* __restrict__ iw, const float* __restrict__ ib,
                              float* __restrict__ out) {
    int idx = blockIdx.x * blockDim.x + threadIdx.x;
    if (idx >= NN*KI) return;
    int i = idx / KI, e = idx % KI;
    const float* p = g_pos[0];
    int cnt = g_icnt[i];
    int j = g_iidx[i*KI + e];
    float mask = (e < cnt) ? 1.0f : 0.0f;
    float dx = p[3*i]-p[3*j], dy = p[3*i+1]-p[3*j+1], dz = p[3*i+2]-p[3*j+2];
    float dist = sqrtf(dx*dx + dy*dy + dz*dz + 1e-12f);
    #pragma unroll
    for (int t = 0; t < 3; t++) {
        const float* iwt = iw + t*258;
        float x = g_dots[t][i] + g_dots[3+t][j] + dist*iwt[256] + (dist/10.0f)*iwt[257] + ib[t];
        out[OFF_S + t*(NN*KI) + i*KI + e] = __fdividef(1.0f, 1.0f + __expf(-x)) * mask;
    }
}

extern "C" void kernel_launch(void* const* d_in, const int* in_sizes, int n_in,
                              void* d_out, int out_size)
{
    const float* h     = (const float*)d_in[0];
    const float* pos   = (const float*)d_in[1];
    const int*   batch = (const int*)  d_in[2];
    const float* ew1   = (const float*)d_in[3];
    const float* eb1   = (const float*)d_in[4];
    const float* ew2   = (const float*)d_in[5];
    const float* eb2   = (const float*)d_in[6];
    const float* cw1   = (const float*)d_in[7];
    const float* cb1   = (const float*)d_in[8];
    const float* cw2   = (const float*)d_in[9];
    const float* nw1   = (const float*)d_in[10];
    const float* nb1   = (const float*)d_in[11];
    const float* nw2   = (const float*)d_in[12];
    const float* nb2   = (const float*)d_in[13];
    const float* fw1   = (const float*)d_in[14];
    const float* fb1   = (const float*)d_in[15];
    const float* fw2   = (const float*)d_in[16];
    const float* fb2   = (const float*)d_in[17];
    const float* iw    = (const float*)d_in[18];
    const float* ib    = (const float*)d_in[19];
    const float* ccw1  = (const float*)d_in[20];
    const float* ccb1  = (const float*)d_in[21];
    const float* ccw2  = (const float*)d_in[22];
    const float* ccb2  = (const float*)d_in[23];
    const float* sw    = (const float*)d_in[24];
    const float* sb    = (const float*)d_in[25];
    float* out = (float*)d_out;

    cudaFuncSetAttribute(edge_mma_kernel, cudaFuncAttributeMaxDynamicSharedMemorySize, EDGE_DSM);

    seg_kernel<<<1, 64>>>(batch);
    init_copy<<<(NN*HH + 255)/256, 256>>>(h, pos);
    wprep_kernel<<<36, 256>>>(ew2, cw1);

    const float cut2[3] = {9.0f, 36.0f, 100.0f};
    int sel = 0;
    for (int l = 0; l < 6; l++) {
        if ((l & 1) == 0)
            neighbors_kernel<KM, false><<<NN/32, 32>>>(sel, batch, cut2[l/2]);
        const float* ew1l = ew1 + l*257*HH;
        pre_kernel<<<NN/8, 256>>>(sel, ew1l, eb1 + l*HH);
        edge_mma_kernel<<<NN/4, 256, EDGE_DSM>>>(sel, l, ew1l + 256*HH,
                                                 eb2 + l*HH, cb1 + l*HH, cw2 + l*HH);
        node_kernel<<<NN/8, HH>>>(sel, nw1 + l*256*HH, nb1 + l*HH,
                                  nw2 + l*HH*HH, nb2 + l*HH);
        sel ^= 1;
    }
    neighbors_kernel<KI, true><<<NN/32, 32>>>(0, batch, 100.0f);
    final_tile_kernel<<<NN/32, HH>>>(fw1, fb1, fw2, fb2,
                                     ccw1, ccb1, ccw2, ccb2, sw, sb, iw, out);
    scores_kernel<<<(NN*KI + 255)/256, 256>>>(iw, ib, out);
}

// round 8
// speedup vs baseline: 2.8087x; 1.3984x over previous
#include <cuda_runtime.h>
#include <cuda_bf16.h>
#include <cstdint>
#include <math.h>

#define NN 4096
#define HH 128
#define KM 32
#define KI 20
#define BB 32
#define SMP 132   // smem row pitch (floats) for staged m
#define NL 12     // per-lane neighbor candidate slots (seg <= 385)

#define OFF_H    0
#define OFF_POS  (NN*HH)
#define OFF_F    (OFF_POS + NN*3)
#define OFF_S    (OFF_F + NN*3)
#define OFF_CONF (OFF_S + 3*NN*KI)
#define OFF_ST   (OFF_CONF + NN*64)

typedef unsigned long long ull;

__device__ float g_h[2][NN*HH];
__device__ float g_pos[2][NN*3];
__device__ float g_A[NN*HH];
__device__ float g_B[NN*HH];
__device__ float g_agg[NN*HH];
__device__ float g_dots[6][NN];
__device__ int   g_idx[NN*KM];
__device__ int   g_cnt[NN];
__device__ int   g_iidx[NN*KI];
__device__ int   g_icnt[NN];
__device__ int   g_seg[BB+1];
// fragment-packed bf16 weights: [l][mat(2)][part(3)][4096] uint2
__device__ __align__(16) uint2 g_Wfrag[36*4096];

__device__ __forceinline__ float silu_f(float x) {
    return __fdividef(x, 1.0f + __expf(-x));
}

// ---- packed fp32x2 scalar GEMM helpers ----
__device__ __forceinline__ ull pack2(float x) {
    ull r; asm("mov.b64 %0, {%1, %1};" : "=l"(r) : "r"(__float_as_uint(x))); return r;
}
__device__ __forceinline__ void ffma2(ull& a, ull v, ull w) {
    asm("fma.rn.f32x2 %0, %1, %2, %0;" : "+l"(a) : "l"(v), "l"(w));
}
__device__ __forceinline__ float2 unpack2(ull a) {
    unsigned lo, hi; asm("mov.b64 {%0, %1}, %2;" : "=r"(lo), "=r"(hi) : "l"(a));
    return make_float2(__uint_as_float(lo), __uint_as_float(hi));
}
template<int NE2, int TP>
__device__ __forceinline__ void gemm_t(ull* acc, const float (*T)[TP],
                                       const float* __restrict__ W, int c, int kk) {
    #pragma unroll 4
    for (int k = 0; k < kk; k++) {
        ull w2 = pack2(W[k*HH + c]);
        const ulonglong2* r = reinterpret_cast<const ulonglong2*>(T[k]);
        #pragma unroll
        for (int q = 0; q < NE2; q++) {
            ulonglong2 v = r[q];
            ffma2(acc[2*q], v.x, w2); ffma2(acc[2*q+1], v.y, w2);
        }
    }
}

// ---- mma.sync helpers ----
__device__ __forceinline__ void mma_bf16(float* d, const uint32_t* a, uint2 b) {
    asm volatile("mma.sync.aligned.m16n8k16.row.col.f32.bf16.bf16.f32 "
        "{%0,%1,%2,%3}, {%4,%5,%6,%7}, {%8,%9}, {%0,%1,%2,%3};"
        : "+f"(d[0]), "+f"(d[1]), "+f"(d[2]), "+f"(d[3])
        : "r"(a[0]), "r"(a[1]), "r"(a[2]), "r"(a[3]), "r"(b.x), "r"(b.y));
}
// 3-way bf16 split of a packed pair
__device__ __forceinline__ void split3x2(float x, float y,
                                         uint32_t& u0, uint32_t& u1, uint32_t& u2) {
    __nv_bfloat162 v0 = __floats2bfloat162_rn(x, y);
    float rx = x - __bfloat162float(v0.x), ry = y - __bfloat162float(v0.y);
    __nv_bfloat162 v1 = __floats2bfloat162_rn(rx, ry);
    rx -= __bfloat162float(v1.x); ry -= __bfloat162float(v1.y);
    __nv_bfloat162 v2 = __floats2bfloat162_rn(rx, ry);
    u0 = *reinterpret_cast<uint32_t*>(&v0);
    u1 = *reinterpret_cast<uint32_t*>(&v1);
    u2 = *reinterpret_cast<uint32_t*>(&v2);
}
__device__ __forceinline__ __nv_bfloat16 wpart3(float w, int part) {
    __nv_bfloat16 p0 = __float2bfloat16(w);
    if (part == 0) return p0;
    float r = w - __bfloat162float(p0);
    __nv_bfloat16 p1 = __float2bfloat16(r);
    if (part == 1) return p1;
    return __float2bfloat16(r - __bfloat162float(p1));
}
// 6-term 3-way-split GEMM for one k-step over 16 n-tiles
__device__ __forceinline__ void gemm6(float (*acc)[4],
                                      const uint32_t* a0, const uint32_t* a1, const uint32_t* a2,
                                      const uint2* __restrict__ p0, const uint2* __restrict__ p1,
                                      const uint2* __restrict__ p2) {
    #pragma unroll
    for (int nt = 0; nt < 16; nt++) mma_bf16(acc[nt], a0, __ldg(p0 + nt*32));
    #pragma unroll
    for (int nt = 0; nt < 16; nt++) mma_bf16(acc[nt], a0, __ldg(p1 + nt*32));
    #pragma unroll
    for (int nt = 0; nt < 16; nt++) mma_bf16(acc[nt], a1, __ldg(p0 + nt*32));
    #pragma unroll
    for (int nt = 0; nt < 16; nt++) mma_bf16(acc[nt], a0, __ldg(p2 + nt*32));
    #pragma unroll
    for (int nt = 0; nt < 16; nt++) mma_bf16(acc[nt], a1, __ldg(p1 + nt*32));
    #pragma unroll
    for (int nt = 0; nt < 16; nt++) mma_bf16(acc[nt], a2, __ldg(p0 + nt*32));
}

// ---- weight prep: pack W[k][n] into mma B-fragment order, 3 parts ----
__global__ void wprep_kernel(const float* __restrict__ ew2, const float* __restrict__ cw1) {
    int b = blockIdx.x;            // b = l*6 + mat*3 + part
    int l = b / 6, mat = (b / 3) % 2, part = b % 3;
    const float* W = (mat ? cw1 : ew2) + l * HH * HH;
    uint2* dst = g_Wfrag + b * 4096;
    for (int idx = threadIdx.x; idx < 4096; idx += blockDim.x) {
        int fg = idx >> 5, lane = idx & 31;
        int ks = fg >> 4, nt = fg & 15, quad = lane >> 2, qt = lane & 3;
        int k0 = ks*16 + qt*2, n = nt*8 + quad;
        __nv_bfloat162 v0, v1;
        v0.x = wpart3(W[k0*HH + n], part);     v0.y = wpart3(W[(k0+1)*HH + n], part);
        v1.x = wpart3(W[(k0+8)*HH + n], part); v1.y = wpart3(W[(k0+9)*HH + n], part);
        uint2 u;
        u.x = *reinterpret_cast<uint32_t*>(&v0);
        u.y = *reinterpret_cast<uint32_t*>(&v1);
        dst[idx] = u;
    }
}

__global__ void seg_kernel(const int* __restrict__ batch) {
    int b = threadIdx.x;
    if (b <= BB) {
        int lo = 0, hi = NN;
        while (lo < hi) { int mid = (lo + hi) >> 1; if (batch[mid] < b) lo = mid + 1; else hi = mid; }
        g_seg[b] = lo;
    }
}
__global__ void init_copy(const float* __restrict__ h, const float* __restrict__ p) {
    int i = blockIdx.x * blockDim.x + threadIdx.x;
    if (i < NN*HH) g_h[0][i] = h[i];
    if (i < NN*3)  g_pos[0][i] = p[i];
}

// ---- warp-per-node radius graph top-k ----
template<int KK, bool INTER>
__global__ __launch_bounds__(128) void neighbors_warp(int sel, const int* __restrict__ batch,
                                                      float cutoff2) {
    const int i = blockIdx.x * 4 + (threadIdx.x >> 5);
    const int lane = threadIdx.x & 31;
    if (i >= NN) return;
    const float* p = g_pos[sel];
    int b = batch[i];
    int s0 = g_seg[b], s1 = g_seg[b+1];
    float px = p[3*i], py = p[3*i+1], pz = p[3*i+2];

    const ull KMAX = ~0ull;
    ull keys[NL];
    #pragma unroll
    for (int q = 0; q < NL; q++) {
        int j = s0 + lane + q*32;
        ull key = KMAX;
        if (j < s1 && j != i) {
            float dx = px - p[3*j], dy = py - p[3*j+1], dz = pz - p[3*j+2];
            float d2 = dx*dx + dy*dy + dz*dz;
            if (d2 <= cutoff2)
                key = ((ull)__float_as_uint(d2) << 32) | (unsigned)j;
        }
        keys[q] = key;
    }
    ull mymin = KMAX;
    #pragma unroll
    for (int q = 0; q < NL; q++) mymin = min(mymin, keys[q]);

    int myout = i;
    int cnt = 0;
    for (int e = 0; e < KK; e++) {
        ull mn = mymin;
        #pragma unroll
        for (int o = 16; o > 0; o >>= 1) {
            ull ot = __shfl_xor_sync(0xffffffffu, mn, o);
            mn = min(mn, ot);
        }
        if (mn == KMAX) break;           // uniform across warp
        if (lane == e) myout = (int)(unsigned)(mn & 0xffffffffu);
        cnt++;
        if (mymin == mn) {               // this lane owned it: consume & rescan
            #pragma unroll
            for (int q = 0; q < NL; q++) if (keys[q] == mn) keys[q] = KMAX;
            mymin = KMAX;
            #pragma unroll
            for (int q = 0; q < NL; q++) mymin = min(mymin, keys[q]);
        }
    }
    int* oi = INTER ? g_iidx : g_idx;
    int* oc = INTER ? g_icnt : g_cnt;
    if (lane < KK) oi[i*KK + lane] = myout;
    if (lane == 0) oc[i] = cnt;
}

// ---- pre: A = h@ew1a + eb1 (wg0), B = h@ew1b (wg1); grid 512 ----
__global__ __launch_bounds__(256) void pre_kernel(int sel, const float* __restrict__ ew1,
                                                  const float* __restrict__ eb1) {
    int n0 = blockIdx.x * 8;
    int c = threadIdx.x & 127, wg = threadIdx.x >> 7;
    const float* h = g_h[sel];
    __shared__ __align__(16) float s_hT[HH][12];
    #pragma unroll
    for (int e = 0; e < 4; e++) s_hT[c][wg*4 + e] = h[(n0 + wg*4 + e)*HH + c];
    __syncthreads();
    ull acc[4];
    ull b2 = wg ? pack2(0.0f) : pack2(eb1[c]);
    #pragma unroll
    for (int q = 0; q < 4; q++) acc[q] = b2;
    gemm_t<2,12>(acc, s_hT, ew1 + wg*HH*HH, c, HH);
    float* outp = wg ? g_B : g_A;
    #pragma unroll
    for (int p = 0; p < 4; p++) {
        float2 f = unpack2(acc[p]);
        outp[(n0+2*p)*HH + c] = f.x; outp[(n0+2*p+1)*HH + c] = f.y;
    }
}

// ---- edge kernel: 4 nodes (128 edge-rows) per CTA, HMMA 3-way-split ----
#define EDGE_DSM (128*SMP*4)

__global__ __launch_bounds__(256) void edge_mma_kernel(
    int sel, int layer,
    const float* __restrict__ ew1d, const float* __restrict__ eb2,
    const float* __restrict__ cb1,  const float* __restrict__ cw2)
{
    extern __shared__ float sM[];   // [128][SMP] staged m (fp32)
    __shared__ int   sJ[128];
    __shared__ float sMask[128], sD2[128], sRel[3*128];
    __shared__ float sWD[128], sEB2[128], sCB1[128], sCW2[128];
    __shared__ float sAgg[8][128];
    __shared__ float sCE[128];

    const int blk = blockIdx.x, tid = threadIdx.x;
    const int w = tid >> 5, lane = tid & 31, quad = lane >> 2, qt = lane & 3;
    const float* p_in = g_pos[sel];
    float* p_out = g_pos[sel^1];

    if (tid < 128) {
        int n = tid >> 5, e = tid & 31, i = 4*blk + n;
        int cnt = g_cnt[i];
        int j = (e < cnt) ? g_idx[i*KM + e] : i;
        sJ[tid] = j;
        sMask[tid] = (e < cnt) ? 1.0f : 0.0f;
        float rx = p_in[3*i] - p_in[3*j], ry = p_in[3*i+1] - p_in[3*j+1], rz = p_in[3*i+2] - p_in[3*j+2];
        sRel[tid] = rx; sRel[128+tid] = ry; sRel[256+tid] = rz;
        sD2[tid] = rx*rx + ry*ry + rz*rz;
        sWD[tid] = ew1d[tid]; sEB2[tid] = eb2[tid]; sCB1[tid] = cb1[tid]; sCW2[tid] = cw2[tid];
    }
    __syncthreads();

    const int iNode = 4*blk + (w >> 1);
    const int r0 = 16*w + quad, r1 = r0 + 8;
    const int j0 = sJ[r0], j1 = sJ[r1];
    const float d20 = sD2[r0], d21 = sD2[r1];
    const float mk0 = sMask[r0], mk1 = sMask[r1];
    const float* gAi = g_A + (size_t)iNode*HH;
    const float* gB0 = g_B + (size_t)j0*HH;
    const float* gB1 = g_B + (size_t)j1*HH;

    const uint2* W1p0 = g_Wfrag + (layer*6 + 0)*4096 + lane;
    const uint2* W1p1 = g_Wfrag + (layer*6 + 1)*4096 + lane;
    const uint2* W1p2 = g_Wfrag + (layer*6 + 2)*4096 + lane;
    const uint2* W2p0 = g_Wfrag + (layer*6 + 3)*4096 + lane;
    const uint2* W2p1 = g_Wfrag + (layer*6 + 4)*4096 + lane;
    const uint2* W2p2 = g_Wfrag + (layer*6 + 5)*4096 + lane;

    float acc[16][4];
    #pragma unroll
    for (int nt = 0; nt < 16; nt++) { acc[nt][0]=0.f; acc[nt][1]=0.f; acc[nt][2]=0.f; acc[nt][3]=0.f; }

    // ---- GEMM1: m1 @ ew2, A frags built on the fly (3-way split) ----
    #pragma unroll
    for (int ks = 0; ks < 8; ks++) {
        int base = ks*16 + qt*2;
        float2 A0 = *reinterpret_cast<const float2*>(gAi + base);
        float2 A8 = *reinterpret_cast<const float2*>(gAi + base + 8);
        float2 B00 = *reinterpret_cast<const float2*>(gB0 + base);
        float2 B08 = *reinterpret_cast<const float2*>(gB0 + base + 8);
        float2 B10 = *reinterpret_cast<const float2*>(gB1 + base);
        float2 B18 = *reinterpret_cast<const float2*>(gB1 + base + 8);
        float2 w0 = *reinterpret_cast<const float2*>(sWD + base);
        float2 w8 = *reinterpret_cast<const float2*>(sWD + base + 8);
        uint32_t a0[4], a1[4], a2[4];
        split3x2(silu_f(fmaf(d20, w0.x, A0.x + B00.x)), silu_f(fmaf(d20, w0.y, A0.y + B00.y)), a0[0], a1[0], a2[0]);
        split3x2(silu_f(fmaf(d21, w0.x, A0.x + B10.x)), silu_f(fmaf(d21, w0.y, A0.y + B10.y)), a0[1], a1[1], a2[1]);
        split3x2(silu_f(fmaf(d20, w8.x, A8.x + B08.x)), silu_f(fmaf(d20, w8.y, A8.y + B08.y)), a0[2], a1[2], a2[2]);
        split3x2(silu_f(fmaf(d21, w8.x, A8.x + B18.x)), silu_f(fmaf(d21, w8.y, A8.y + B18.y)), a0[3], a1[3], a2[3]);
        gemm6(acc, a0, a1, a2, W1p0 + ks*512, W1p1 + ks*512, W1p2 + ks*512);
    }

    // ---- epilogue1: m = silu(D1+eb2)*mask -> sM (fp32, same-thread reuse) + agg ----
    #pragma unroll
    for (int nt = 0; nt < 16; nt++) {
        int cc = nt*8 + qt*2;
        float m00 = silu_f(acc[nt][0] + sEB2[cc])   * mk0;
        float m01 = silu_f(acc[nt][1] + sEB2[cc+1]) * mk0;
        float m10 = silu_f(acc[nt][2] + sEB2[cc])   * mk1;
        float m11 = silu_f(acc[nt][3] + sEB2[cc+1]) * mk1;
        sM[r0*SMP + cc]   = m00; sM[r0*SMP + cc+1] = m01;
        sM[r1*SMP + cc]   = m10; sM[r1*SMP + cc+1] = m11;
        float s0 = m00 + m10, s1 = m01 + m11;
        #pragma unroll
        for (int off = 4; off <= 16; off <<= 1) {
            s0 += __shfl_xor_sync(0xffffffffu, s0, off);
            s1 += __shfl_xor_sync(0xffffffffu, s1, off);
        }
        if (quad == 0) { sAgg[w][cc] = s0; sAgg[w][cc+1] = s1; }
        acc[nt][0] = 0.f; acc[nt][1] = 0.f; acc[nt][2] = 0.f; acc[nt][3] = 0.f;
    }

    // ---- GEMM2: m @ cw1 (A re-split from sM, same-thread data) ----
    #pragma unroll
    for (int ks = 0; ks < 8; ks++) {
        int k0 = ks*16 + qt*2;
        float2 x00 = *reinterpret_cast<const float2*>(sM + r0*SMP + k0);
        float2 x10 = *reinterpret_cast<const float2*>(sM + r1*SMP + k0);
        float2 x08 = *reinterpret_cast<const float2*>(sM + r0*SMP + k0 + 8);
        float2 x18 = *reinterpret_cast<const float2*>(sM + r1*SMP + k0 + 8);
        uint32_t a0[4], a1[4], a2[4];
        split3x2(x00.x, x00.y, a0[0], a1[0], a2[0]);
        split3x2(x10.x, x10.y, a0[1], a1[1], a2[1]);
        split3x2(x08.x, x08.y, a0[2], a1[2], a2[2]);
        split3x2(x18.x, x18.y, a0[3], a1[3], a2[3]);
        gemm6(acc, a0, a1, a2, W2p0 + ks*512, W2p1 + ks*512, W2p2 + ks*512);
    }

    // ---- epilogue2: per-edge coord scalar cE = sum_c silu(D2+cb1)*cw2 ----
    float p0 = 0.f, p1 = 0.f;
    #pragma unroll
    for (int nt = 0; nt < 16; nt++) {
        int cc = nt*8 + qt*2;
        p0 += silu_f(acc[nt][0] + sCB1[cc])*sCW2[cc] + silu_f(acc[nt][1] + sCB1[cc+1])*sCW2[cc+1];
        p1 += silu_f(acc[nt][2] + sCB1[cc])*sCW2[cc] + silu_f(acc[nt][3] + sCB1[cc+1])*sCW2[cc+1];
    }
    p0 += __shfl_xor_sync(0xffffffffu, p0, 1); p0 += __shfl_xor_sync(0xffffffffu, p0, 2);
    p1 += __shfl_xor_sync(0xffffffffu, p1, 1); p1 += __shfl_xor_sync(0xffffffffu, p1, 2);
    if (qt == 0) { sCE[r0] = p0; sCE[r1] = p1; }
    __syncthreads();

    // agg combine
    #pragma unroll
    for (int rep = 0; rep < 2; rep++) {
        int idx = tid + 256*rep;
        int n = idx >> 7, c = idx & 127;
        g_agg[(4*blk + n)*HH + c] = sAgg[2*n][c] + sAgg[2*n+1][c];
    }

    // coord update
    if (w < 4) {
        int r = 32*w + lane, i = 4*blk + w;
        float ce = sCE[r], mk = sMask[r];
        float fx = sRel[r]*ce*mk, fy = sRel[128+r]*ce*mk, fz = sRel[256+r]*ce*mk;
        #pragma unroll
        for (int o = 16; o > 0; o >>= 1) {
            fx += __shfl_down_sync(0xffffffffu, fx, o);
            fy += __shfl_down_sync(0xffffffffu, fy, o);
            fz += __shfl_down_sync(0xffffffffu, fz, o);
        }
        if (lane == 0) {
            float cnt = fmaxf((float)g_cnt[i], 1.0f);
            p_out[3*i+0] = p_in[3*i+0] + fx / cnt;
            p_out[3*i+1] = p_in[3*i+1] + fy / cnt;
            p_out[3*i+2] = p_in[3*i+2] + fz / cnt;
        }
    }
}

// ---- node MLP: TILE=8, grid=512 ----
__global__ __launch_bounds__(HH) void node_kernel(
    int sel,
    const float* __restrict__ nw1, const float* __restrict__ nb1,
    const float* __restrict__ nw2, const float* __restrict__ nb2)
{
    int n0 = blockIdx.x * 8, c = threadIdx.x;
    const float* h_in = g_h[sel];
    float* h_out = g_h[sel^1];
    __shared__ __align__(16) float s_hT[HH][12];
    __shared__ __align__(16) float s_aT[HH][12];
    #pragma unroll
    for (int e = 0; e < 8; e++) s_hT[c][e] = h_in[(n0+e)*HH + c];
    #pragma unroll
    for (int e = 0; e < 8; e++) s_aT[c][e] = g_agg[(n0+e)*HH + c];
    __syncthreads();

    ull acc[4];
    ull b2 = pack2(nb1[c]);
    #pragma unroll
    for (int q = 0; q < 4; q++) acc[q] = b2;
    gemm_t<2,12>(acc, s_hT, nw1, c, HH);
    gemm_t<2,12>(acc, s_aT, nw1 + HH*HH, c, HH);
    __syncthreads();
    #pragma unroll
    for (int p = 0; p < 4; p++) {
        float2 f = unpack2(acc[p]);
        s_aT[c][2*p] = silu_f(f.x); s_aT[c][2*p+1] = silu_f(f.y);
    }
    __syncthreads();
    b2 = pack2(nb2[c]);
    #pragma unroll
    for (int q = 0; q < 4; q++) acc[q] = b2;
    gemm_t<2,12>(acc, s_aT, nw2, c, HH);
    #pragma unroll
    for (int p = 0; p < 4; p++) {
        float2 f = unpack2(acc[p]);
        h_out[(n0+2*p)*HH + c]   = s_hT[c][2*p]   + f.x;
        h_out[(n0+2*p+1)*HH + c] = s_hT[c][2*p+1] + f.y;
    }
}

// ---- final readout (TILE=32) ----
__global__ __launch_bounds__(HH) void final_tile_kernel(
    const float* __restrict__ fw1, const float* __restrict__ fb1,
    const float* __restrict__ fw2, const float* __restrict__ fb2,
    const float* __restrict__ ccw1, const float* __restrict__ ccb1,
    const float* __restrict__ ccw2, const float* __restrict__ ccb2,
    const float* __restrict__ sw,  const float* __restrict__ sb,
    const float* __restrict__ iw,
    float* __restrict__ out)
{
    int n0 = blockIdx.x * 32, c = threadIdx.x;
    const float* h = g_h[0];
    const float* p = g_pos[0];
    __shared__ __align__(16) float s_hT[HH][36];
    __shared__ __align__(16) float s_tT[HH][36];

    #pragma unroll
    for (int e = 0; e < 32; e++) {
        float v = h[(n0+e)*HH + c];
        s_hT[c][e] = v;
        out[OFF_H + (n0+e)*HH + c] = v;
    }
    if (c < 3)
        for (int e = 0; e < 32; e++) out[OFF_POS + (n0+e)*3 + c] = p[(n0+e)*3 + c];
    __syncthreads();

    ull acc[16];
    ull b2 = pack2(fb1[c]);
    #pragma unroll
    for (int q = 0; q < 16; q++) acc[q] = b2;
    gemm_t<8,36>(acc, s_hT, fw1, c, HH);
    #pragma unroll
    for (int p2 = 0; p2 < 16; p2++) {
        float2 f = unpack2(acc[p2]);
        s_tT[c][2*p2] = tanhf(f.x); s_tT[c][2*p2+1] = tanhf(f.y);
    }
    __syncthreads();
    if (c < 96) {
        int e = c / 3, t = c % 3;
        float s = 0.0f;
        #pragma unroll 8
        for (int k = 0; k < HH; k++) s += s_tT[k][e] * fw2[k*3 + t];
        out[OFF_F + (n0+e)*3 + t] = s + fb2[t];
    }
    if (c < 32) {
        float s = 0.0f;
        #pragma unroll 8
        for (int k = 0; k < HH; k++) s += s_hT[k][c] * sw[k];
        out[OFF_ST + n0 + c] = s + sb[0];
        #pragma unroll
        for (int t = 0; t < 3; t++) {
            float da = 0.0f, db = 0.0f;
            const float* iwt = iw + t*258;
            #pragma unroll 8
            for (int k = 0; k < HH; k++) {
                float hv = s_hT[k][c];
                da += hv * iwt[k]; db += hv * iwt[128 + k];
            }
            g_dots[t][n0 + c] = da; g_dots[3+t][n0 + c] = db;
        }
    }
    __syncthreads();

    b2 = pack2(ccb1[c]);
    #pragma unroll
    for (int q = 0; q < 16; q++) acc[q] = b2;
    gemm_t<8,36>(acc, s_hT, ccw1, c, HH);
    #pragma unroll
    for (int p2 = 0; p2 < 16; p2++) {
        float2 f = unpack2(acc[p2]);
        s_tT[c][2*p2] = fmaxf(f.x, 0.0f); s_tT[c][2*p2+1] = fmaxf(f.y, 0.0f);
    }
    __syncthreads();
    if (c < 64) {
        ull bb = pack2(ccb2[c]);
        #pragma unroll
        for (int q = 0; q < 16; q++) acc[q] = bb;
        #pragma unroll 4
        for (int k = 0; k < HH; k++) {
            ull w2 = pack2(ccw2[k*64 + c]);
            const ulonglong2* r = reinterpret_cast<const ulonglong2*>(s_tT[k]);
            #pragma unroll
            for (int q = 0; q < 8; q++) {
                ulonglong2 v = r[q];
                ffma2(acc[2*q], v.x, w2); ffma2(acc[2*q+1], v.y, w2);
            }
        }
        #pragma unroll
        for (int p2 = 0; p2 < 16; p2++) {
            float2 f = unpack2(acc[p2]);
            out[OFF_CONF + (n0+2*p2)*64 + c]   = f.x;
            out[OFF_CONF + (n0+2*p2+1)*64 + c] = f.y;
        }
    }
}

__global__ void scores_kernel(const float* __restrict__ iw, const float* __restrict__ ib,
                              float* __restrict__ out) {
    int idx = blockIdx.x * blockDim.x + threadIdx.x;
    if (idx >= NN*KI) return;
    int i = idx / KI, e = idx % KI;
    const float* p = g_pos[0];
    int cnt = g_icnt[i];
    int j = g_iidx[i*KI + e];
    float mask = (e < cnt) ? 1.0f : 0.0f;
    float dx = p[3*i]-p[3*j], dy = p[3*i+1]-p[3*j+1], dz = p[3*i+2]-p[3*j+2];
    float dist = sqrtf(dx*dx + dy*dy + dz*dz + 1e-12f);
    #pragma unroll
    for (int t = 0; t < 3; t++) {
        const float* iwt = iw + t*258;
        float x = g_dots[t][i] + g_dots[3+t][j] + dist*iwt[256] + (dist/10.0f)*iwt[257] + ib[t];
        out[OFF_S + t*(NN*KI) + i*KI + e] = __fdividef(1.0f, 1.0f + __expf(-x)) * mask;
    }
}

extern "C" void kernel_launch(void* const* d_in, const int* in_sizes, int n_in,
                              void* d_out, int out_size)
{
    const float* h     = (const float*)d_in[0];
    const float* pos   = (const float*)d_in[1];
    const int*   batch = (const int*)  d_in[2];
    const float* ew1   = (const float*)d_in[3];
    const float* eb1   = (const float*)d_in[4];
    const float* ew2   = (const float*)d_in[5];
    const float* eb2   = (const float*)d_in[6];
    const float* cw1   = (const float*)d_in[7];
    const float* cb1   = (const float*)d_in[8];
    const float* cw2   = (const float*)d_in[9];
    const float* nw1   = (const float*)d_in[10];
    const float* nb1   = (const float*)d_in[11];
    const float* nw2   = (const float*)d_in[12];
    const float* nb2   = (const float*)d_in[13];
    const float* fw1   = (const float*)d_in[14];
    const float* fb1   = (const float*)d_in[15];
    const float* fw2   = (const float*)d_in[16];
    const float* fb2   = (const float*)d_in[17];
    const float* iw    = (const float*)d_in[18];
    const float* ib    = (const float*)d_in[19];
    const float* ccw1  = (const float*)d_in[20];
    const float* ccb1  = (const float*)d_in[21];
    const float* ccw2  = (const float*)d_in[22];
    const float* ccb2  = (const float*)d_in[23];
    const float* sw    = (const float*)d_in[24];
    const float* sb    = (const float*)d_in[25];
    float* out = (float*)d_out;

    cudaFuncSetAttribute(edge_mma_kernel, cudaFuncAttributeMaxDynamicSharedMemorySize, EDGE_DSM);

    seg_kernel<<<1, 64>>>(batch);
    init_copy<<<(NN*HH + 255)/256, 256>>>(h, pos);
    wprep_kernel<<<36, 256>>>(ew2, cw1);

    const float cut2[3] = {9.0f, 36.0f, 100.0f};
    int sel = 0;
    for (int l = 0; l < 6; l++) {
        if ((l & 1) == 0)
            neighbors_warp<KM, false><<<NN/4, 128>>>(sel, batch, cut2[l/2]);
        const float* ew1l = ew1 + l*257*HH;
        pre_kernel<<<NN/8, 256>>>(sel, ew1l, eb1 + l*HH);
        edge_mma_kernel<<<NN/4, 256, EDGE_DSM>>>(sel, l, ew1l + 256*HH,
                                                 eb2 + l*HH, cb1 + l*HH, cw2 + l*HH);
        node_kernel<<<NN/8, HH>>>(sel, nw1 + l*256*HH, nb1 + l*HH,
                                  nw2 + l*HH*HH, nb2 + l*HH);
        sel ^= 1;
    }
    neighbors_warp<KI, true><<<NN/4, 128>>>(0, batch, 100.0f);
    final_tile_kernel<<<NN/32, HH>>>(fw1, fb1, fw2, fb2,
                                     ccw1, ccb1, ccw2, ccb2, sw, sb, iw, out);
    scores_kernel<<<(NN*KI + 255)/256, 256>>>(iw, ib, out);
}

// round 11
// speedup vs baseline: 2.9888x; 1.0641x over previous
#include <cuda_runtime.h>
#include <cuda_bf16.h>
#include <cstdint>
#include <math.h>

#define NN 4096
#define HH 128
#define KM 32
#define KI 20
#define BB 32
#define SMP 132
#define NL 12

#define OFF_H    0
#define OFF_POS  (NN*HH)
#define OFF_F    (OFF_POS + NN*3)
#define OFF_S    (OFF_F + NN*3)
#define OFF_CONF (OFF_S + 3*NN*KI)
#define OFF_ST   (OFF_CONF + NN*64)

typedef unsigned long long ull;

__device__ float g_h[2][NN*HH];
__device__ float g_pos[2][NN*3];
__device__ float g_A[NN*HH];
__device__ float g_B[NN*HH];
__device__ float g_agg[NN*HH];
__device__ float g_dots[6][NN];
__device__ int   g_idx[NN*KM];
__device__ int   g_cnt[NN];
__device__ int   g_iidx[NN*KI];
__device__ int   g_icnt[NN];
__device__ int   g_seg[BB+1];
// fragment-packed bf16 weights: [l*4 + mat*2... ] -> [(l*2+mat)*3+part][4096] uint2 (mats: ew2, cw1)
__device__ __align__(16) uint2 g_Wfrag[36*4096];

__device__ __forceinline__ float silu_f(float x) {
    return __fdividef(x, 1.0f + __expf(-x));
}

// ---- packed fp32x2 scalar GEMM helpers ----
__device__ __forceinline__ ull pack2(float x) {
    ull r; asm("mov.b64 %0, {%1, %1};" : "=l"(r) : "r"(__float_as_uint(x))); return r;
}
__device__ __forceinline__ void ffma2(ull& a, ull v, ull w) {
    asm("fma.rn.f32x2 %0, %1, %2, %0;" : "+l"(a) : "l"(v), "l"(w));
}
__device__ __forceinline__ float2 unpack2(ull a) {
    unsigned lo, hi; asm("mov.b64 {%0, %1}, %2;" : "=r"(lo), "=r"(hi) : "l"(a));
    return make_float2(__uint_as_float(lo), __uint_as_float(hi));
}
template<int NE2, int TP>
__device__ __forceinline__ void gemm_t(ull* acc, const float (*T)[TP],
                                       const float* __restrict__ W, int c, int kk) {
    #pragma unroll 4
    for (int k = 0; k < kk; k++) {
        ull w2 = pack2(W[k*HH + c]);
        const ulonglong2* r = reinterpret_cast<const ulonglong2*>(T[k]);
        #pragma unroll
        for (int q = 0; q < NE2; q++) {
            ulonglong2 v = r[q];
            ffma2(acc[2*q], v.x, w2); ffma2(acc[2*q+1], v.y, w2);
        }
    }
}

// ---- mma.sync helpers ----
__device__ __forceinline__ void mma_bf16(float* d, const uint32_t* a, uint2 b) {
    asm volatile("mma.sync.aligned.m16n8k16.row.col.f32.bf16.bf16.f32 "
        "{%0,%1,%2,%3}, {%4,%5,%6,%7}, {%8,%9}, {%0,%1,%2,%3};"
        : "+f"(d[0]), "+f"(d[1]), "+f"(d[2]), "+f"(d[3])
        : "r"(a[0]), "r"(a[1]), "r"(a[2]), "r"(a[3]), "r"(b.x), "r"(b.y));
}
__device__ __forceinline__ void split3x2(float x, float y,
                                         uint32_t& u0, uint32_t& u1, uint32_t& u2) {
    __nv_bfloat162 v0 = __floats2bfloat162_rn(x, y);
    float rx = x - __bfloat162float(v0.x), ry = y - __bfloat162float(v0.y);
    __nv_bfloat162 v1 = __floats2bfloat162_rn(rx, ry);
    rx -= __bfloat162float(v1.x); ry -= __bfloat162float(v1.y);
    __nv_bfloat162 v2 = __floats2bfloat162_rn(rx, ry);
    u0 = *reinterpret_cast<uint32_t*>(&v0);
    u1 = *reinterpret_cast<uint32_t*>(&v1);
    u2 = *reinterpret_cast<uint32_t*>(&v2);
}
__device__ __forceinline__ __nv_bfloat16 wpart3(float w, int part) {
    __nv_bfloat16 p0 = __float2bfloat16(w);
    if (part == 0) return p0;
    float r = w - __bfloat162float(p0);
    __nv_bfloat16 p1 = __float2bfloat16(r);
    if (part == 1) return p1;
    return __float2bfloat16(r - __bfloat162float(p1));
}
// 6-term 3-way-split GEMM for one k-step over 16 n-tiles (R8-validated)
__device__ __forceinline__ void gemm6(float (*acc)[4],
                                      const uint32_t* a0, const uint32_t* a1, const uint32_t* a2,
                                      const uint2* __restrict__ p0, const uint2* __restrict__ p1,
                                      const uint2* __restrict__ p2) {
    #pragma unroll
    for (int nt = 0; nt < 16; nt++) mma_bf16(acc[nt], a0, __ldg(p0 + nt*32));
    #pragma unroll
    for (int nt = 0; nt < 16; nt++) mma_bf16(acc[nt], a0, __ldg(p1 + nt*32));
    #pragma unroll
    for (int nt = 0; nt < 16; nt++) mma_bf16(acc[nt], a1, __ldg(p0 + nt*32));
    #pragma unroll
    for (int nt = 0; nt < 16; nt++) mma_bf16(acc[nt], a0, __ldg(p2 + nt*32));
    #pragma unroll
    for (int nt = 0; nt < 16; nt++) mma_bf16(acc[nt], a1, __ldg(p1 + nt*32));
    #pragma unroll
    for (int nt = 0; nt < 16; nt++) mma_bf16(acc[nt], a2, __ldg(p0 + nt*32));
}
__device__ __forceinline__ void gemm_sT(float (*acc)[4], const float* sT,
                                        int r0, int r1, int qt,
                                        const uint2* p0, const uint2* p1, const uint2* p2) {
    #pragma unroll
    for (int ks = 0; ks < 8; ks++) {
        int k0 = ks*16 + qt*2;
        float2 x00 = *reinterpret_cast<const float2*>(sT + r0*SMP + k0);
        float2 x10 = *reinterpret_cast<const float2*>(sT + r1*SMP + k0);
        float2 x08 = *reinterpret_cast<const float2*>(sT + r0*SMP + k0 + 8);
        float2 x18 = *reinterpret_cast<const float2*>(sT + r1*SMP + k0 + 8);
        uint32_t a0[4], a1[4], a2[4];
        split3x2(x00.x, x00.y, a0[0], a1[0], a2[0]);
        split3x2(x10.x, x10.y, a0[1], a1[1], a2[1]);
        split3x2(x08.x, x08.y, a0[2], a1[2], a2[2]);
        split3x2(x18.x, x18.y, a0[3], a1[3], a2[3]);
        gemm6(acc, a0, a1, a2, p0 + ks*512, p1 + ks*512, p2 + ks*512);
    }
}

// ---- weight prep: pack ew2/cw1 into mma B-fragment order, 3 parts ----
__global__ void wprep_kernel(const float* __restrict__ ew2, const float* __restrict__ cw1) {
    int b = blockIdx.x;            // b = (l*2+mat)*3+part, grid 36
    int part = b % 3, mat = (b / 3) % 2, l = b / 6;
    const float* W = (mat ? cw1 : ew2) + l * HH * HH;
    uint2* dst = g_Wfrag + (size_t)b * 4096;
    for (int idx = threadIdx.x; idx < 4096; idx += blockDim.x) {
        int fg = idx >> 5, lane = idx & 31;
        int ks = fg >> 4, nt = fg & 15, quad = lane >> 2, qt = lane & 3;
        int k0 = ks*16 + qt*2, n = nt*8 + quad;
        __nv_bfloat162 v0, v1;
        v0.x = wpart3(W[k0*HH + n], part);     v0.y = wpart3(W[(k0+1)*HH + n], part);
        v1.x = wpart3(W[(k0+8)*HH + n], part); v1.y = wpart3(W[(k0+9)*HH + n], part);
        uint2 u;
        u.x = *reinterpret_cast<uint32_t*>(&v0);
        u.y = *reinterpret_cast<uint32_t*>(&v1);
        dst[idx] = u;
    }
}

__global__ void seg_kernel(const int* __restrict__ batch) {
    int b = threadIdx.x;
    if (b <= BB) {
        int lo = 0, hi = NN;
        while (lo < hi) { int mid = (lo + hi) >> 1; if (batch[mid] < b) lo = mid + 1; else hi = mid; }
        g_seg[b] = lo;
    }
}
__global__ void init_copy(const float* __restrict__ h, const float* __restrict__ p) {
    int i = blockIdx.x * blockDim.x + threadIdx.x;
    if (i < NN*HH) g_h[0][i] = h[i];
    if (i < NN*3)  g_pos[0][i] = p[i];
}

// ---- warp-per-node radius graph top-k ----
template<int KK, bool INTER>
__global__ __launch_bounds__(128) void neighbors_warp(int sel, const int* __restrict__ batch,
                                                      float cutoff2) {
    const int i = blockIdx.x * 4 + (threadIdx.x >> 5);
    const int lane = threadIdx.x & 31;
    if (i >= NN) return;
    const float* p = g_pos[sel];
    int b = batch[i];
    int s0 = g_seg[b], s1 = g_seg[b+1];
    float px = p[3*i], py = p[3*i+1], pz = p[3*i+2];

    const ull KMAX = ~0ull;
    ull keys[NL];
    #pragma unroll
    for (int q = 0; q < NL; q++) {
        int j = s0 + lane + q*32;
        ull key = KMAX;
        if (j < s1 && j != i) {
            float dx = px - p[3*j], dy = py - p[3*j+1], dz = pz - p[3*j+2];
            float d2 = dx*dx + dy*dy + dz*dz;
            if (d2 <= cutoff2)
                key = ((ull)__float_as_uint(d2) << 32) | (unsigned)j;
        }
        keys[q] = key;
    }
    ull mymin = KMAX;
    #pragma unroll
    for (int q = 0; q < NL; q++) mymin = min(mymin, keys[q]);

    int myout = i;
    int cnt = 0;
    for (int e = 0; e < KK; e++) {
        ull mn = mymin;
        #pragma unroll
        for (int o = 16; o > 0; o >>= 1) {
            ull ot = __shfl_xor_sync(0xffffffffu, mn, o);
            mn = min(mn, ot);
        }
        if (mn == KMAX) break;
        if (lane == e) myout = (int)(unsigned)(mn & 0xffffffffu);
        cnt++;
        if (mymin == mn) {
            #pragma unroll
            for (int q = 0; q < NL; q++) if (keys[q] == mn) keys[q] = KMAX;
            mymin = KMAX;
            #pragma unroll
            for (int q = 0; q < NL; q++) mymin = min(mymin, keys[q]);
        }
    }
    int* oi = INTER ? g_iidx : g_idx;
    int* oc = INTER ? g_icnt : g_cnt;
    if (lane < KK) oi[i*KK + lane] = myout;
    if (lane == 0) oc[i] = cnt;
}

// ---- pre: A = h@ew1a + eb1 (wg0), B = h@ew1b (wg1); fp32 scalar, grid 512 ----
__global__ __launch_bounds__(256) void pre_kernel(int sel, const float* __restrict__ ew1,
                                                  const float* __restrict__ eb1) {
    int n0 = blockIdx.x * 8;
    int c = threadIdx.x & 127, wg = threadIdx.x >> 7;
    const float* h = g_h[sel];
    __shared__ __align__(16) float s_hT[HH][12];
    #pragma unroll
    for (int e = 0; e < 4; e++) s_hT[c][wg*4 + e] = h[(n0 + wg*4 + e)*HH + c];
    __syncthreads();
    ull acc[4];
    ull b2 = wg ? pack2(0.0f) : pack2(eb1[c]);
    #pragma unroll
    for (int q = 0; q < 4; q++) acc[q] = b2;
    gemm_t<2,12>(acc, s_hT, ew1 + wg*HH*HH, c, HH);
    float* outp = wg ? g_B : g_A;
    #pragma unroll
    for (int p = 0; p < 4; p++) {
        float2 f = unpack2(acc[p]);
        outp[(n0+2*p)*HH + c] = f.x; outp[(n0+2*p+1)*HH + c] = f.y;
    }
}

// ---- edge kernel: 4 nodes/CTA, 6-term HMMA, dead-half skip ----
#define EDGE_DSM (128*SMP*4)

__global__ __launch_bounds__(256) void edge_mma_kernel(
    int sel, int layer,
    const float* __restrict__ ew1d, const float* __restrict__ eb2,
    const float* __restrict__ cb1,  const float* __restrict__ cw2)
{
    extern __shared__ float sM[];
    __shared__ int   sJ[128], sCnt[4];
    __shared__ float sMask[128], sD2[128], sRel[3*128];
    __shared__ float sWD[128], sEB2[128], sCB1[128], sCW2[128];
    __shared__ float sAgg[8][128];
    __shared__ float sCE[128];

    const int blk = blockIdx.x, tid = threadIdx.x;
    const int w = tid >> 5, lane = tid & 31, quad = lane >> 2, qt = lane & 3;
    // warp -> (node, edge-half): dead halves pair with live halves on the same SMSP
    const int nid = w & 3, half = w >> 2;
    const int r0 = (nid << 5) + (half << 4) + quad, r1 = r0 + 8;
    const float* p_in = g_pos[sel];
    float* p_out = g_pos[sel^1];

    if (tid < 4) sCnt[tid] = g_cnt[4*blk + tid];
    if (tid < 128) {
        int n = tid >> 5, e = tid & 31, i = 4*blk + n;
        int cnt = g_cnt[i];
        int j = (e < cnt) ? g_idx[i*KM + e] : i;
        sJ[tid] = j;
        sMask[tid] = (e < cnt) ? 1.0f : 0.0f;
        float rx = p_in[3*i] - p_in[3*j], ry = p_in[3*i+1] - p_in[3*j+1], rz = p_in[3*i+2] - p_in[3*j+2];
        sRel[tid] = rx; sRel[128+tid] = ry; sRel[256+tid] = rz;
        sD2[tid] = rx*rx + ry*ry + rz*rz;
        sWD[tid] = ew1d[tid]; sEB2[tid] = eb2[tid]; sCB1[tid] = cb1[tid]; sCW2[tid] = cw2[tid];
    }
    __syncthreads();

    const bool live = sCnt[nid] > half * 16;
    if (live) {
        const int iNode = 4*blk + nid;
        const int j0 = sJ[r0], j1 = sJ[r1];
        const float d20 = sD2[r0], d21 = sD2[r1];
        const float mk0 = sMask[r0], mk1 = sMask[r1];
        const float* gAi = g_A + (size_t)iNode*HH;
        const float* gB0 = g_B + (size_t)j0*HH;
        const float* gB1 = g_B + (size_t)j1*HH;

        const uint2* Wg = g_Wfrag + (size_t)layer*6*4096;
        const uint2* W1p0 = Wg + lane;
        const uint2* W1p1 = Wg + 4096 + lane;
        const uint2* W1p2 = Wg + 2*4096 + lane;
        const uint2* W2p0 = Wg + 3*4096 + lane;
        const uint2* W2p1 = Wg + 4*4096 + lane;
        const uint2* W2p2 = Wg + 5*4096 + lane;

        float acc[16][4];
        #pragma unroll
        for (int nt = 0; nt < 16; nt++) { acc[nt][0]=0.f; acc[nt][1]=0.f; acc[nt][2]=0.f; acc[nt][3]=0.f; }

        // GEMM1: m1 @ ew2, A frags built on the fly
        #pragma unroll
        for (int ks = 0; ks < 8; ks++) {
            int base = ks*16 + qt*2;
            float2 A0 = *reinterpret_cast<const float2*>(gAi + base);
            float2 A8 = *reinterpret_cast<const float2*>(gAi + base + 8);
            float2 B00 = *reinterpret_cast<const float2*>(gB0 + base);
            float2 B08 = *reinterpret_cast<const float2*>(gB0 + base + 8);
            float2 B10 = *reinterpret_cast<const float2*>(gB1 + base);
            float2 B18 = *reinterpret_cast<const float2*>(gB1 + base + 8);
            float2 w0 = *reinterpret_cast<const float2*>(sWD + base);
            float2 w8 = *reinterpret_cast<const float2*>(sWD + base + 8);
            uint32_t a0[4], a1[4], a2[4];
            split3x2(silu_f(fmaf(d20, w0.x, A0.x + B00.x)), silu_f(fmaf(d20, w0.y, A0.y + B00.y)), a0[0], a1[0], a2[0]);
            split3x2(silu_f(fmaf(d21, w0.x, A0.x + B10.x)), silu_f(fmaf(d21, w0.y, A0.y + B10.y)), a0[1], a1[1], a2[1]);
            split3x2(silu_f(fmaf(d20, w8.x, A8.x + B08.x)), silu_f(fmaf(d20, w8.y, A8.y + B08.y)), a0[2], a1[2], a2[2]);
            split3x2(silu_f(fmaf(d21, w8.x, A8.x + B18.x)), silu_f(fmaf(d21, w8.y, A8.y + B18.y)), a0[3], a1[3], a2[3]);
            gemm6(acc, a0, a1, a2, W1p0 + ks*512, W1p1 + ks*512, W1p2 + ks*512);
        }

        // epilogue1: m = silu(D1+eb2)*mask -> sM + agg
        #pragma unroll
        for (int nt = 0; nt < 16; nt++) {
            int cc = nt*8 + qt*2;
            float m00 = silu_f(acc[nt][0] + sEB2[cc])   * mk0;
            float m01 = silu_f(acc[nt][1] + sEB2[cc+1]) * mk0;
            float m10 = silu_f(acc[nt][2] + sEB2[cc])   * mk1;
            float m11 = silu_f(acc[nt][3] + sEB2[cc+1]) * mk1;
            sM[r0*SMP + cc]   = m00; sM[r0*SMP + cc+1] = m01;
            sM[r1*SMP + cc]   = m10; sM[r1*SMP + cc+1] = m11;
            float s0 = m00 + m10, s1 = m01 + m11;
            #pragma unroll
            for (int off = 4; off <= 16; off <<= 1) {
                s0 += __shfl_xor_sync(0xffffffffu, s0, off);
                s1 += __shfl_xor_sync(0xffffffffu, s1, off);
            }
            if (quad == 0) { sAgg[w][cc] = s0; sAgg[w][cc+1] = s1; }
            acc[nt][0] = 0.f; acc[nt][1] = 0.f; acc[nt][2] = 0.f; acc[nt][3] = 0.f;
        }

        // GEMM2: m @ cw1
        gemm_sT(acc, sM, r0, r1, qt, W2p0, W2p1, W2p2);

        // epilogue2: per-edge coord scalar
        float p0 = 0.f, p1 = 0.f;
        #pragma unroll
        for (int nt = 0; nt < 16; nt++) {
            int cc = nt*8 + qt*2;
            p0 += silu_f(acc[nt][0] + sCB1[cc])*sCW2[cc] + silu_f(acc[nt][1] + sCB1[cc+1])*sCW2[cc+1];
            p1 += silu_f(acc[nt][2] + sCB1[cc])*sCW2[cc] + silu_f(acc[nt][3] + sCB1[cc+1])*sCW2[cc+1];
        }
        p0 += __shfl_xor_sync(0xffffffffu, p0, 1); p0 += __shfl_xor_sync(0xffffffffu, p0, 2);
        p1 += __shfl_xor_sync(0xffffffffu, p1, 1); p1 += __shfl_xor_sync(0xffffffffu, p1, 2);
        if (qt == 0) { sCE[r0] = p0; sCE[r1] = p1; }
    } else {
        for (int x = lane; x < 128; x += 32) sAgg[w][x] = 0.f;
        if (qt == 0) { sCE[r0] = 0.f; sCE[r1] = 0.f; }
    }
    __syncthreads();

    // agg combine: node n <- warps n (half0) + n+4 (half1)
    #pragma unroll
    for (int rep = 0; rep < 2; rep++) {
        int idx = tid + 256*rep;
        int n = idx >> 7, c = idx & 127;
        g_agg[(4*blk + n)*HH + c] = sAgg[n][c] + sAgg[n+4][c];
    }

    // coord update: warp n = node n, lane = edge
    if (w < 4) {
        int r = 32*w + lane, i = 4*blk + w;
        float ce = sCE[r], mk = sMask[r];
        float fx = sRel[r]*ce*mk, fy = sRel[128+r]*ce*mk, fz = sRel[256+r]*ce*mk;
        #pragma unroll
        for (int o = 16; o > 0; o >>= 1) {
            fx += __shfl_down_sync(0xffffffffu, fx, o);
            fy += __shfl_down_sync(0xffffffffu, fy, o);
            fz += __shfl_down_sync(0xffffffffu, fz, o);
        }
        if (lane == 0) {
            float cnt = fmaxf((float)g_cnt[i], 1.0f);
            p_out[3*i+0] = p_in[3*i+0] + fx / cnt;
            p_out[3*i+1] = p_in[3*i+1] + fy / cnt;
            p_out[3*i+2] = p_in[3*i+2] + fz / cnt;
        }
    }
}

// ---- node MLP: fp32 scalar, TILE=8, grid=512 ----
__global__ __launch_bounds__(HH) void node_kernel(
    int sel,
    const float* __restrict__ nw1, const float* __restrict__ nb1,
    const float* __restrict__ nw2, const float* __restrict__ nb2)
{
    int n0 = blockIdx.x * 8, c = threadIdx.x;
    const float* h_in = g_h[sel];
    float* h_out = g_h[sel^1];
    __shared__ __align__(16) float s_hT[HH][12];
    __shared__ __align__(16) float s_aT[HH][12];
    #pragma unroll
    for (int e = 0; e < 8; e++) s_hT[c][e] = h_in[(n0+e)*HH + c];
    #pragma unroll
    for (int e = 0; e < 8; e++) s_aT[c][e] = g_agg[(n0+e)*HH + c];
    __syncthreads();

    ull acc[4];
    ull b2 = pack2(nb1[c]);
    #pragma unroll
    for (int q = 0; q < 4; q++) acc[q] = b2;
    gemm_t<2,12>(acc, s_hT, nw1, c, HH);
    gemm_t<2,12>(acc, s_aT, nw1 + HH*HH, c, HH);
    __syncthreads();
    #pragma unroll
    for (int p = 0; p < 4; p++) {
        float2 f = unpack2(acc[p]);
        s_aT[c][2*p] = silu_f(f.x); s_aT[c][2*p+1] = silu_f(f.y);
    }
    __syncthreads();
    b2 = pack2(nb2[c]);
    #pragma unroll
    for (int q = 0; q < 4; q++) acc[q] = b2;
    gemm_t<2,12>(acc, s_aT, nw2, c, HH);
    #pragma unroll
    for (int p = 0; p < 4; p++) {
        float2 f = unpack2(acc[p]);
        h_out[(n0+2*p)*HH + c]   = s_hT[c][2*p]   + f.x;
        h_out[(n0+2*p+1)*HH + c] = s_hT[c][2*p+1] + f.y;
    }
}

// ---- final readout (TILE=32) ----
__global__ __launch_bounds__(HH) void final_tile_kernel(
    const float* __restrict__ fw1, const float* __restrict__ fb1,
    const float* __restrict__ fw2, const float* __restrict__ fb2,
    const float* __restrict__ ccw1, const float* __restrict__ ccb1,
    const float* __restrict__ ccw2, const float* __restrict__ ccb2,
    const float* __restrict__ sw,  const float* __restrict__ sb,
    const float* __restrict__ iw,
    float* __restrict__ out)
{
    int n0 = blockIdx.x * 32, c = threadIdx.x;
    const float* h = g_h[0];
    const float* p = g_pos[0];
    __shared__ __align__(16) float s_hT[HH][36];
    __shared__ __align__(16) float s_tT[HH][36];

    #pragma unroll
    for (int e = 0; e < 32; e++) {
        float v = h[(n0+e)*HH + c];
        s_hT[c][e] = v;
        out[OFF_H + (n0+e)*HH + c] = v;
    }
    if (c < 3)
        for (int e = 0; e < 32; e++) out[OFF_POS + (n0+e)*3 + c] = p[(n0+e)*3 + c];
    __syncthreads();

    ull acc[16];
    ull b2 = pack2(fb1[c]);
    #pragma unroll
    for (int q = 0; q < 16; q++) acc[q] = b2;
    gemm_t<8,36>(acc, s_hT, fw1, c, HH);
    #pragma unroll
    for (int p2 = 0; p2 < 16; p2++) {
        float2 f = unpack2(acc[p2]);
        s_tT[c][2*p2] = tanhf(f.x); s_tT[c][2*p2+1] = tanhf(f.y);
    }
    __syncthreads();
    if (c < 96) {
        int e = c / 3, t = c % 3;
        float s = 0.0f;
        #pragma unroll 8
        for (int k = 0; k < HH; k++) s += s_tT[k][e] * fw2[k*3 + t];
        out[OFF_F + (n0+e)*3 + t] = s + fb2[t];
    }
    if (c < 32) {
        float s = 0.0f;
        #pragma unroll 8
        for (int k = 0; k < HH; k++) s += s_hT[k][c] * sw[k];
        out[OFF_ST + n0 + c] = s + sb[0];
        #pragma unroll
        for (int t = 0; t < 3; t++) {
            float da = 0.0f, db = 0.0f;
            const float* iwt = iw + t*258;
            #pragma unroll 8
            for (int k = 0; k < HH; k++) {
                float hv = s_hT[k][c];
                da += hv * iwt[k]; db += hv * iwt[128 + k];
            }
            g_dots[t][n0 + c] = da; g_dots[3+t][n0 + c] = db;
        }
    }
    __syncthreads();

    b2 = pack2(ccb1[c]);
    #pragma unroll
    for (int q = 0; q < 16; q++) acc[q] = b2;
    gemm_t<8,36>(acc, s_hT, ccw1, c, HH);
    #pragma unroll
    for (int p2 = 0; p2 < 16; p2++) {
        float2 f = unpack2(acc[p2]);
        s_tT[c][2*p2] = fmaxf(f.x, 0.0f); s_tT[c][2*p2+1] = fmaxf(f.y, 0.0f);
    }
    __syncthreads();
    if (c < 64) {
        ull bb = pack2(ccb2[c]);
        #pragma unroll
        for (int q = 0; q < 16; q++) acc[q] = bb;
        #pragma unroll 4
        for (int k = 0; k < HH; k++) {
            ull w2 = pack2(ccw2[k*64 + c]);
            const ulonglong2* r = reinterpret_cast<const ulonglong2*>(s_tT[k]);
            #pragma unroll
            for (int q = 0; q < 8; q++) {
                ulonglong2 v = r[q];
                ffma2(acc[2*q], v.x, w2); ffma2(acc[2*q+1], v.y, w2);
            }
        }
        #pragma unroll
        for (int p2 = 0; p2 < 16; p2++) {
            float2 f = unpack2(acc[p2]);
            out[OFF_CONF + (n0+2*p2)*64 + c]   = f.x;
            out[OFF_CONF + (n0+2*p2+1)*64 + c] = f.y;
        }
    }
}

__global__ void scores_kernel(const float* __restrict__ iw, const float* __restrict__ ib,
                              float* __restrict__ out) {
    int idx = blockIdx.x * blockDim.x + threadIdx.x;
    if (idx >= NN*KI) return;
    int i = idx / KI, e = idx % KI;
    const float* p = g_pos[0];
    int cnt = g_icnt[i];
    int j = g_iidx[i*KI + e];
    float mask = (e < cnt) ? 1.0f : 0.0f;
    float dx = p[3*i]-p[3*j], dy = p[3*i+1]-p[3*j+1], dz = p[3*i+2]-p[3*j+2];
    float dist = sqrtf(dx*dx + dy*dy + dz*dz + 1e-12f);
    #pragma unroll
    for (int t = 0; t < 3; t++) {
        const float* iwt = iw + t*258;
        float x = g_dots[t][i] + g_dots[3+t][j] + dist*iwt[256] + (dist/10.0f)*iwt[257] + ib[t];
        out[OFF_S + t*(NN*KI) + i*KI + e] = __fdividef(1.0f, 1.0f + __expf(-x)) * mask;
    }
}

extern "C" void kernel_launch(void* const* d_in, const int* in_sizes, int n_in,
                              void* d_out, int out_size)
{
    const float* h     = (const float*)d_in[0];
    const float* pos   = (const float*)d_in[1];
    const int*   batch = (const int*)  d_in[2];
    const float* ew1   = (const float*)d_in[3];
    const float* eb1   = (const float*)d_in[4];
    const float* ew2   = (const float*)d_in[5];
    const float* eb2   = (const float*)d_in[6];
    const float* cw1   = (const float*)d_in[7];
    const float* cb1   = (const float*)d_in[8];
    const float* cw2   = (const float*)d_in[9];
    const float* nw1   = (const float*)d_in[10];
    const float* nb1   = (const float*)d_in[11];
    const float* nw2   = (const float*)d_in[12];
    const float* nb2   = (const float*)d_in[13];
    const float* fw1   = (const float*)d_in[14];
    const float* fb1   = (const float*)d_in[15];
    const float* fw2   = (const float*)d_in[16];
    const float* fb2   = (const float*)d_in[17];
    const float* iw    = (const float*)d_in[18];
    const float* ib    = (const float*)d_in[19];
    const float* ccw1  = (const float*)d_in[20];
    const float* ccb1  = (const float*)d_in[21];
    const float* ccw2  = (const float*)d_in[22];
    const float* ccb2  = (const float*)d_in[23];
    const float* sw    = (const float*)d_in[24];
    const float* sb    = (const float*)d_in[25];
    float* out = (float*)d_out;

    cudaFuncSetAttribute(edge_mma_kernel, cudaFuncAttributeMaxDynamicSharedMemorySize, EDGE_DSM);

    seg_kernel<<<1, 64>>>(batch);
    init_copy<<<(NN*HH + 255)/256, 256>>>(h, pos);
    wprep_kernel<<<36, 256>>>(ew2, cw1);

    const float cut2[3] = {9.0f, 36.0f, 100.0f};
    int sel = 0;
    for (int l = 0; l < 6; l++) {
        if ((l & 1) == 0)
            neighbors_warp<KM, false><<<NN/4, 128>>>(sel, batch, cut2[l/2]);
        const float* ew1l = ew1 + l*257*HH;
        pre_kernel<<<NN/8, 256>>>(sel, ew1l, eb1 + l*HH);
        edge_mma_kernel<<<NN/4, 256, EDGE_DSM>>>(sel, l, ew1l + 256*HH,
                                                 eb2 + l*HH, cb1 + l*HH, cw2 + l*HH);
        node_kernel<<<NN/8, HH>>>(sel, nw1 + l*256*HH, nb1 + l*HH,
                                  nw2 + l*HH*HH, nb2 + l*HH);
        sel ^= 1;
    }
    neighbors_warp<KI, true><<<NN/4, 128>>>(0, batch, 100.0f);
    final_tile_kernel<<<NN/32, HH>>>(fw1, fb1, fw2, fb2,
                                     ccw1, ccb1, ccw2, ccb2, sw, sb, iw, out);
    scores_kernel<<<(NN*KI + 255)/256, 256>>>(iw, ib, out);
}